// round 1
// baseline (speedup 1.0000x reference)
#include <cuda_runtime.h>
#include <cuda_bf16.h>

// Problem shapes (fixed by reference)
#define Bn   4
#define Hn   16
#define Tn   512
#define Mn   512
#define Dn   64
#define HIDn 16

constexpr int TILE     = 64;     // T-tile and M-tile
constexpr int NTHREADS = 512;
constexpr int PITCH    = 68;     // floats per row for 64-wide smem tiles (17 float4)
constexpr int PITCH4   = 17;
constexpr int SPITCH   = 520;    // score row pitch (512 + 8 -> bank-stagger)

// dyn smem layout: Qs[64*68] | Ks[64*68] (reused as Vs) | Ds[64*68] | S[64*520]
constexpr int SMEM_FLOATS = 3 * TILE * PITCH + TILE * SPITCH;
constexpr int SMEM_BYTES  = SMEM_FLOATS * 4;

extern __shared__ float smem[];

__global__ __launch_bounds__(NTHREADS, 1)
void msmha_kernel(const float* __restrict__ qg,
                  const float* __restrict__ kg,
                  const float* __restrict__ vg,
                  const float* __restrict__ dtm,
                  const float* __restrict__ w1g,   // (H,2,16)
                  const float* __restrict__ b1g,   // (H,16)
                  const float* __restrict__ w2g,   // (H,16,1)
                  const float* __restrict__ b2g,   // (H,1)
                  float* __restrict__ outg)        // (B,T,H*Dn)
{
    const int tt  = blockIdx.x;          // 0..7  (T tile)
    const int bh  = blockIdx.y;          // 0..63
    const int b   = bh >> 4;
    const int h   = bh & 15;
    const int t0  = tt * TILE;
    const int tid = threadIdx.x;

    float* Qs = smem;
    float* Ks = Qs + TILE * PITCH;       // reused as Vs in phase 3
    float* Ds = Ks + TILE * PITCH;
    float* S  = Ds + TILE * PITCH;

    // ---- per-head MLP weights into registers (uniform across block) ----
    float w1d[HIDn], w1x[HIDn], bb1[HIDn], ww2[HIDn];
    {
        const float* W1 = w1g + h * 2 * HIDn;
        const float* B1 = b1g + h * HIDn;
        const float* W2 = w2g + h * HIDn;
#pragma unroll
        for (int j = 0; j < HIDn; ++j) {
            w1d[j] = W1[j];
            w1x[j] = W1[HIDn + j];
            bb1[j] = B1[j];
            ww2[j] = W2[j];
        }
    }
    const float bias2 = b2g[h];

    // ---- load Q tile, pre-scaled by 1/sqrt(64) = 0.125 ----
    {
        const float4* src = reinterpret_cast<const float4*>(qg + ((long)bh * Tn + t0) * Dn);
        float4* dst = reinterpret_cast<float4*>(Qs);
        for (int i = tid; i < TILE * 16; i += NTHREADS) {
            int row = i >> 4, c4 = i & 15;
            float4 v = src[row * 16 + c4];
            v.x *= 0.125f; v.y *= 0.125f; v.z *= 0.125f; v.w *= 0.125f;
            dst[row * PITCH4 + c4] = v;
        }
    }

    // ================= Phase 1: mixed scores into S =================
    // thread -> (row pair rp, m-group mg); m values = mg + 16*j (stride-16
    // across threads keeps Ks float4 reads at 2-way conflicts max)
    const int rp = tid >> 4;     // 0..31
    const int mg = tid & 15;     // 0..15
    const int r0 = rp * 2;

    for (int mt = 0; mt < Mn / TILE; ++mt) {
        const int m0 = mt * TILE;

        // cooperative load of K tile and D tile
        {
            const float4* ksrc = reinterpret_cast<const float4*>(kg + ((long)bh * Mn + m0) * Dn);
            float4* kdst = reinterpret_cast<float4*>(Ks);
            const float4* dsrc = reinterpret_cast<const float4*>(dtm + ((long)b * Tn + t0) * Mn + m0);
            float4* ddst = reinterpret_cast<float4*>(Ds);
            for (int i = tid; i < TILE * 16; i += NTHREADS) {
                int row = i >> 4, c4 = i & 15;
                kdst[row * PITCH4 + c4] = ksrc[row * 16 + c4];
                // D row stride in gmem is Mn floats = 128 float4
                ddst[row * PITCH4 + c4] = dsrc[row * 128 + c4];
            }
        }
        __syncthreads();

        // dot products: 2 rows x 4 m per thread
        float acc0[4] = {0.f, 0.f, 0.f, 0.f};
        float acc1[4] = {0.f, 0.f, 0.f, 0.f};
        const float4* Qs4 = reinterpret_cast<const float4*>(Qs);
        const float4* Ks4 = reinterpret_cast<const float4*>(Ks);
#pragma unroll
        for (int k4 = 0; k4 < 16; ++k4) {
            float4 qa = Qs4[r0 * PITCH4 + k4];
            float4 qb = Qs4[(r0 + 1) * PITCH4 + k4];
#pragma unroll
            for (int j = 0; j < 4; ++j) {
                float4 kv = Ks4[(mg + 16 * j) * PITCH4 + k4];
                acc0[j] = fmaf(qa.x, kv.x, acc0[j]);
                acc0[j] = fmaf(qa.y, kv.y, acc0[j]);
                acc0[j] = fmaf(qa.z, kv.z, acc0[j]);
                acc0[j] = fmaf(qa.w, kv.w, acc0[j]);
                acc1[j] = fmaf(qb.x, kv.x, acc1[j]);
                acc1[j] = fmaf(qb.y, kv.y, acc1[j]);
                acc1[j] = fmaf(qb.z, kv.z, acc1[j]);
                acc1[j] = fmaf(qb.w, kv.w, acc1[j]);
            }
        }

        // MLP(dot, D) -> mixed score, store to S
#pragma unroll
        for (int i = 0; i < 2; ++i) {
            const int row = r0 + i;
#pragma unroll
            for (int j = 0; j < 4; ++j) {
                const int mloc = mg + 16 * j;
                const float dotv = (i == 0) ? acc0[j] : acc1[j];
                const float Dv   = Ds[row * PITCH + mloc];
                float s = bias2;
#pragma unroll
                for (int jj = 0; jj < HIDn; ++jj) {
                    float hv = fmaf(dotv, w1d[jj], fmaf(Dv, w1x[jj], bb1[jj]));
                    hv = fmaxf(hv, 0.f);
                    s = fmaf(hv, ww2[jj], s);
                }
                S[row * SPITCH + m0 + mloc] = s;
            }
        }
        __syncthreads();
    }

    // ================= Phase 2: softmax over M (512) ================
    // 8 lanes per row (contiguous lanes -> safe shfl groups)
    const int r = tid >> 3;     // 0..63
    const int l = tid & 7;      // 0..7

    float mx = -1e30f;
#pragma unroll
    for (int i = 0; i < Mn / 8; ++i)
        mx = fmaxf(mx, S[r * SPITCH + l + 8 * i]);
#pragma unroll
    for (int o = 4; o; o >>= 1)
        mx = fmaxf(mx, __shfl_xor_sync(0xffffffffu, mx, o));

    float sum = 0.f;
#pragma unroll
    for (int i = 0; i < Mn / 8; ++i) {
        float p = __expf(S[r * SPITCH + l + 8 * i] - mx);
        S[r * SPITCH + l + 8 * i] = p;
        sum += p;
    }
#pragma unroll
    for (int o = 4; o; o >>= 1)
        sum += __shfl_xor_sync(0xffffffffu, sum, o);
    const float inv = 1.0f / sum;

    // ================= Phase 3: O = P @ V =================
    // thread owns row r, d-columns {4l..4l+3} and {32+4l..32+4l+3}
    float o0[8] = {0.f, 0.f, 0.f, 0.f, 0.f, 0.f, 0.f, 0.f};

    for (int mt = 0; mt < Mn / TILE; ++mt) {
        const int m0 = mt * TILE;
        // load V tile into Ks buffer
        {
            const float4* vsrc = reinterpret_cast<const float4*>(vg + ((long)bh * Mn + m0) * Dn);
            float4* vdst = reinterpret_cast<float4*>(Ks);
            for (int i = tid; i < TILE * 16; i += NTHREADS) {
                int row = i >> 4, c4 = i & 15;
                vdst[row * PITCH4 + c4] = vsrc[row * 16 + c4];
            }
        }
        __syncthreads();

        const float4* Vs4 = reinterpret_cast<const float4*>(Ks);
#pragma unroll 8
        for (int mm = 0; mm < TILE; ++mm) {
            const float p = S[r * SPITCH + m0 + mm];
            float4 va = Vs4[mm * PITCH4 + l];        // d-cols 4l..4l+3
            float4 vb = Vs4[mm * PITCH4 + 8 + l];    // d-cols 32+4l..
            o0[0] = fmaf(p, va.x, o0[0]);
            o0[1] = fmaf(p, va.y, o0[1]);
            o0[2] = fmaf(p, va.z, o0[2]);
            o0[3] = fmaf(p, va.w, o0[3]);
            o0[4] = fmaf(p, vb.x, o0[4]);
            o0[5] = fmaf(p, vb.y, o0[5]);
            o0[6] = fmaf(p, vb.z, o0[6]);
            o0[7] = fmaf(p, vb.w, o0[7]);
        }
        __syncthreads();
    }

    // normalize and store: out[b][t0+r][h*64 + dcol]
    {
        float* op = outg + ((long)b * Tn + t0 + r) * (Hn * Dn) + h * Dn;
        float4 ra = {o0[0] * inv, o0[1] * inv, o0[2] * inv, o0[3] * inv};
        float4 rb = {o0[4] * inv, o0[5] * inv, o0[6] * inv, o0[7] * inv};
        reinterpret_cast<float4*>(op + 4 * l)[0]      = ra;
        reinterpret_cast<float4*>(op + 32 + 4 * l)[0] = rb;
    }
}

extern "C" void kernel_launch(void* const* d_in, const int* in_sizes, int n_in,
                              void* d_out, int out_size)
{
    const float* q   = (const float*)d_in[0];
    const float* k   = (const float*)d_in[1];
    const float* v   = (const float*)d_in[2];
    const float* dtm = (const float*)d_in[3];
    const float* w1  = (const float*)d_in[4];
    const float* b1  = (const float*)d_in[5];
    const float* w2  = (const float*)d_in[6];
    const float* b2  = (const float*)d_in[7];
    float* out = (float*)d_out;

    cudaFuncSetAttribute(msmha_kernel,
                         cudaFuncAttributeMaxDynamicSharedMemorySize, SMEM_BYTES);

    dim3 grid(Tn / TILE, Bn * Hn);   // (8, 64)
    msmha_kernel<<<grid, NTHREADS, SMEM_BYTES>>>(q, k, v, dtm, w1, b1, w2, b2, out);
}

// round 2
// speedup vs baseline: 1.0190x; 1.0190x over previous
#include <cuda_runtime.h>
#include <cuda_bf16.h>

// Problem shapes (fixed)
#define Bn   4
#define Hn   16
#define Tn   512
#define Mn   512
#define Dn   64
#define HIDn 16

typedef unsigned long long ull;

constexpr int NTHREADS = 512;
constexpr int TILE_T   = 64;     // rows per CTA
constexpr int MCH      = 128;    // m-chunk
constexpr int QP       = 68;     // Q pitch (floats), 17 float4
constexpr int KP       = 130;    // Kt pitch over m (even -> LDS.64 aligned)
constexpr int DP       = 132;    // D pitch (mult of 4 -> float4 stores)
constexpr int VP       = 68;     // V pitch
constexpr int SPITCH   = 520;    // score pitch

// smem: Qs[64*68] | Kt[64*130] | Ds[64*132] | S[64*520];  Vs overlays Kt/Ds
constexpr int QS_OFF = 0;
constexpr int KT_OFF = QS_OFF + TILE_T * QP;          // 4352
constexpr int DS_OFF = KT_OFF + Dn * KP;              // +8320
constexpr int S_OFF  = DS_OFF + TILE_T * DP;          // +8448
constexpr int SMEM_FLOATS = S_OFF + TILE_T * SPITCH;  // +33280 = 54400
constexpr int SMEM_BYTES  = SMEM_FLOATS * 4;          // 217600 B

extern __shared__ float smem[];

// ---------- f32x2 helpers (PTX-only on sm_10x) ----------
__device__ __forceinline__ ull pk2(float lo, float hi) {
    ull r; asm("mov.b64 %0, {%1,%2};" : "=l"(r) : "f"(lo), "f"(hi)); return r;
}
__device__ __forceinline__ ull dup2(float v) { return pk2(v, v); }
__device__ __forceinline__ void un2(ull v, float& a, float& b) {
    asm("mov.b64 {%0,%1}, %2;" : "=f"(a), "=f"(b) : "l"(v));
}
__device__ __forceinline__ ull f2fma(ull a, ull b, ull c) {
    ull d; asm("fma.rn.f32x2 %0, %1, %2, %3;" : "=l"(d) : "l"(a), "l"(b), "l"(c)); return d;
}
__device__ __forceinline__ ull f2add(ull a, ull b) {
    ull d; asm("add.rn.f32x2 %0, %1, %2;" : "=l"(d) : "l"(a), "l"(b)); return d;
}

__global__ __launch_bounds__(NTHREADS, 1)
void msmha_kernel(const float* __restrict__ qg,
                  const float* __restrict__ kg,
                  const float* __restrict__ vg,
                  const float* __restrict__ dtm,
                  const float* __restrict__ w1g,   // (H,2,16)
                  const float* __restrict__ b1g,   // (H,16)
                  const float* __restrict__ w2g,   // (H,16,1)
                  const float* __restrict__ b2g,   // (H,1)
                  float* __restrict__ outg)        // (B,T,H*Dn)
{
    const int tt  = blockIdx.x;            // T tile 0..7
    const int bh  = blockIdx.y;            // 0..63
    const int b   = bh >> 4;
    const int h   = bh & 15;
    const int t0  = tt * TILE_T;
    const int tid = threadIdx.x;
    const int wid = tid >> 5;              // 0..15
    const int lane = tid & 31;

    float* Qs = smem + QS_OFF;
    float* Kt = smem + KT_OFF;
    float* Ds = smem + DS_OFF;
    float* S  = smem + S_OFF;
    float* Vs = Kt;                        // overlay for phase 3

    // ---- per-head MLP weights as packed scalar pairs (64 regs) ----
    ull w1d2[8], w1x2[8], b12[8], w2h2[8];
    {
        const float* W1 = w1g + h * 2 * HIDn;
        const float* B1 = b1g + h * HIDn;
        const float* W2 = w2g + h * HIDn;
#pragma unroll
        for (int jp = 0; jp < 8; ++jp) {
            w1d2[jp] = pk2(W1[2*jp],        W1[2*jp+1]);
            w1x2[jp] = pk2(W1[HIDn+2*jp],   W1[HIDn+2*jp+1]);
            b12[jp]  = pk2(B1[2*jp],        B1[2*jp+1]);
            w2h2[jp] = pk2(0.5f*W2[2*jp],   0.5f*W2[2*jp+1]);  // fold relu=0.5*(h+|h|)
        }
    }
    const float bias2 = b2g[h];

    // ---- Q tile, prescaled by 1/8 ----
    {
        const float4* src = reinterpret_cast<const float4*>(qg + ((long)bh * Tn + t0) * Dn);
#pragma unroll
        for (int it = 0; it < 2; ++it) {
            int i = tid + NTHREADS * it;
            int row = i >> 4, c4 = i & 15;
            float4 v = src[row * 16 + c4];
            v.x *= 0.125f; v.y *= 0.125f; v.z *= 0.125f; v.w *= 0.125f;
            *reinterpret_cast<float4*>(Qs + row * QP + 4*c4) = v;
        }
    }

    // ============ Phase 1: scores (QK dot + MLP), m-chunks of 128 ============
    const int r0 = 4 * wid;       // warp owns rows r0..r0+3

    for (int mc = 0; mc < Mn / MCH; ++mc) {
        const int m0 = mc * MCH;
        // Kt: transposed K chunk [d][m]; conflict-free STS (lanes->consecutive m)
#pragma unroll
        for (int it = 0; it < 4; ++it) {
            int idx = tid + NTHREADS * it;
            int d4 = idx >> 7, m = idx & 127;
            float4 kv = *reinterpret_cast<const float4*>(kg + ((long)bh * Mn + m0 + m) * Dn + 4*d4);
            Kt[(4*d4+0) * KP + m] = kv.x;
            Kt[(4*d4+1) * KP + m] = kv.y;
            Kt[(4*d4+2) * KP + m] = kv.z;
            Kt[(4*d4+3) * KP + m] = kv.w;
        }
        // D chunk [t][m]
#pragma unroll
        for (int it = 0; it < 4; ++it) {
            int idx = tid + NTHREADS * it;
            int rr = idx >> 5, c4 = idx & 31;
            float4 dv = *reinterpret_cast<const float4*>(dtm + ((long)b * Tn + t0 + rr) * Mn + m0 + 4*c4);
            *reinterpret_cast<float4*>(Ds + rr * DP + 4*c4) = dv;
        }
        __syncthreads();

        // dot: 4 rows x 2 m-pairs per thread, packed over (m, m+1)
        ull acc[4][2];
#pragma unroll
        for (int i = 0; i < 4; ++i) { acc[i][0] = 0ull; acc[i][1] = 0ull; }

        const float4* Qs4 = reinterpret_cast<const float4*>(Qs);
#pragma unroll 4
        for (int d4 = 0; d4 < 16; ++d4) {
            float4 qv[4];
#pragma unroll
            for (int i = 0; i < 4; ++i) qv[i] = Qs4[(r0 + i) * (QP/4) + d4];
#pragma unroll
            for (int dd = 0; dd < 4; ++dd) {
                const int d = 4*d4 + dd;
                ull ka = *reinterpret_cast<const ull*>(Kt + d * KP + 2*lane);
                ull kb = *reinterpret_cast<const ull*>(Kt + d * KP + 64 + 2*lane);
#pragma unroll
                for (int i = 0; i < 4; ++i) {
                    float q = reinterpret_cast<const float*>(&qv[i])[dd];
                    ull qd = dup2(q);
                    acc[i][0] = f2fma(qd, ka, acc[i][0]);
                    acc[i][1] = f2fma(qd, kb, acc[i][1]);
                }
            }
        }

        // MLP over hidden-pairs; relu via h + |h| with folded 0.5*w2
#pragma unroll
        for (int i = 0; i < 4; ++i) {
            const int row = r0 + i;
#pragma unroll
            for (int p = 0; p < 2; ++p) {
                const int mloc = 2*lane + 64*p;
                float da, db; un2(acc[i][p], da, db);
                ull D2 = *reinterpret_cast<const ull*>(Ds + row * DP + mloc);
                float Da, Db; un2(D2, Da, Db);
                float out2[2];
#pragma unroll
                for (int sc = 0; sc < 2; ++sc) {
                    ull dd2 = dup2(sc ? db : da);
                    ull DD2 = dup2(sc ? Db : Da);
                    ull s2 = 0ull;
#pragma unroll
                    for (int jp = 0; jp < 8; ++jp) {
                        ull base = f2fma(DD2, w1x2[jp], b12[jp]);
                        ull hh   = f2fma(dd2, w1d2[jp], base);
                        ull rr2  = f2add(hh, hh & 0x7FFFFFFF7FFFFFFFull);
                        s2 = f2fma(rr2, w2h2[jp], s2);
                    }
                    float slo, shi; un2(s2, slo, shi);
                    out2[sc] = slo + shi + bias2;
                }
                *reinterpret_cast<float2*>(S + row * SPITCH + m0 + mloc) =
                    make_float2(out2[0], out2[1]);
            }
        }
        __syncthreads();
    }

    // ============ Phase 2: softmax with FMA-based exp2 ============
    const int r  = tid >> 3;     // 0..63
    const int l8 = tid & 7;      // 0..7
    float* Sr = S + r * SPITCH;

    float mx = -1e30f;
#pragma unroll 8
    for (int i = 0; i < 32; ++i) {
        float2 v = *reinterpret_cast<const float2*>(Sr + 2*(l8 + 8*i));
        mx = fmaxf(mx, fmaxf(v.x, v.y));
    }
#pragma unroll
    for (int o = 4; o; o >>= 1)
        mx = fmaxf(mx, __shfl_xor_sync(0xffffffffu, mx, o));

    const ull L2E2  = dup2(1.44269504f);
    const ull MAG2  = dup2(12582912.0f);
    const ull NMAG2 = dup2(-12582912.0f);
    const ull NONE2 = dup2(-1.0f);
    const ull ONE2  = dup2(1.0f);
    const ull TC1   = dup2(0.69314718056f);
    const ull TC2   = dup2(0.240226507f);
    const ull TC3   = dup2(0.0555041087f);
    const ull TC4   = dup2(0.00961812911f);
    const ull TC5   = dup2(0.00133335581f);
    const ull CM2   = dup2(-mx * 1.44269504f);

    float sum = 0.f;
#pragma unroll 4
    for (int i = 0; i < 32; ++i) {
        float* sp = Sr + 2*(l8 + 8*i);
        ull x2  = *reinterpret_cast<const ull*>(sp);
        ull a2  = f2fma(x2, L2E2, CM2);        // t = (x-mx)*log2e
        ull fr2 = f2add(a2, MAG2);             // round-to-int magic
        ull nf2 = f2add(fr2, NMAG2);           // n as float
        ull ff2 = f2fma(nf2, NONE2, a2);       // f = t - n  in [-0.5,0.5]
        ull p2  = f2fma(TC5, ff2, TC4);        // 2^f Taylor-5
        p2 = f2fma(p2, ff2, TC3);
        p2 = f2fma(p2, ff2, TC2);
        p2 = f2fma(p2, ff2, TC1);
        p2 = f2fma(p2, ff2, ONE2);
        float frl, frh, pl, ph;
        un2(fr2, frl, frh); un2(p2, pl, ph);
        // exponent insert: bits(fr)<<23 == n<<23 (magic low 9 bits are 0)
        float yl = __int_as_float(__float_as_int(pl) + (__float_as_int(frl) << 23));
        float yh = __int_as_float(__float_as_int(ph) + (__float_as_int(frh) << 23));
        *reinterpret_cast<float2*>(sp) = make_float2(yl, yh);
        sum += yl + yh;
    }
#pragma unroll
    for (int o = 4; o; o >>= 1)
        sum += __shfl_xor_sync(0xffffffffu, sum, o);
    const float inv = 1.0f / sum;
    __syncthreads();

    // ============ Phase 3: O = P @ V, packed over d-pairs ============
    ull o2[4] = {0ull, 0ull, 0ull, 0ull};

    for (int mc = 0; mc < Mn / MCH; ++mc) {
        const int m0 = mc * MCH;
#pragma unroll
        for (int it = 0; it < 4; ++it) {
            int idx = tid + NTHREADS * it;
            int row = idx >> 4, c4 = idx & 15;
            float4 vv = *reinterpret_cast<const float4*>(vg + ((long)bh * Mn + m0 + row) * Dn + 4*c4);
            *reinterpret_cast<float4*>(Vs + row * VP + 4*c4) = vv;
        }
        __syncthreads();

        const float* Sp = S + r * SPITCH + m0;
#pragma unroll 8
        for (int mm = 0; mm < MCH; ++mm) {
            float p = Sp[mm];
            ull pd = dup2(p);
            const ull* vrow = reinterpret_cast<const ull*>(Vs + mm * VP);
            o2[0] = f2fma(pd, vrow[2*l8],      o2[0]);   // d = 4*l8 .. +1
            o2[1] = f2fma(pd, vrow[2*l8 + 1],  o2[1]);   // d = 4*l8+2 ..
            o2[2] = f2fma(pd, vrow[16 + 2*l8], o2[2]);   // d = 32+4*l8 ..
            o2[3] = f2fma(pd, vrow[16 + 2*l8 + 1], o2[3]);
        }
        __syncthreads();
    }

    // epilogue: normalize + store
    {
        float ox[8];
        un2(o2[0], ox[0], ox[1]); un2(o2[1], ox[2], ox[3]);
        un2(o2[2], ox[4], ox[5]); un2(o2[3], ox[6], ox[7]);
        float* op = outg + ((long)b * Tn + t0 + r) * (Hn * Dn) + h * Dn;
        float4 ra = {ox[0]*inv, ox[1]*inv, ox[2]*inv, ox[3]*inv};
        float4 rb = {ox[4]*inv, ox[5]*inv, ox[6]*inv, ox[7]*inv};
        *reinterpret_cast<float4*>(op + 4*l8)      = ra;
        *reinterpret_cast<float4*>(op + 32 + 4*l8) = rb;
    }
}

extern "C" void kernel_launch(void* const* d_in, const int* in_sizes, int n_in,
                              void* d_out, int out_size)
{
    const float* q   = (const float*)d_in[0];
    const float* k   = (const float*)d_in[1];
    const float* v   = (const float*)d_in[2];
    const float* dtm = (const float*)d_in[3];
    const float* w1  = (const float*)d_in[4];
    const float* b1  = (const float*)d_in[5];
    const float* w2  = (const float*)d_in[6];
    const float* b2  = (const float*)d_in[7];
    float* out = (float*)d_out;

    cudaFuncSetAttribute(msmha_kernel,
                         cudaFuncAttributeMaxDynamicSharedMemorySize, SMEM_BYTES);

    dim3 grid(Tn / TILE_T, Bn * Hn);   // (8, 64)
    msmha_kernel<<<grid, NTHREADS, SMEM_BYTES>>>(q, k, v, dtm, w1, b1, w2, b2, out);
}

// round 3
// speedup vs baseline: 1.0733x; 1.0533x over previous
#include <cuda_runtime.h>
#include <cuda_bf16.h>

// Problem shapes (fixed)
#define Bn   4
#define Hn   16
#define Tn   512
#define Mn   512
#define Dn   64
#define HIDn 16

typedef unsigned long long ull;

constexpr int NTHREADS = 512;
constexpr int TILE_T   = 64;     // rows per CTA
constexpr int MCH      = 128;    // m-chunk
constexpr int QP       = 68;     // Q pitch (floats), 17 float4
constexpr int KP       = 130;    // Kt pitch over m (even -> LDS.64 aligned)
constexpr int DP       = 132;    // D pitch (mult of 4 -> float4 stores)
constexpr int VP       = 68;     // V pitch
constexpr int SPITCH   = 520;    // score pitch

// smem: Qs[64*68] | Kt[64*130] | Ds[64*132] | S[64*520];  Vs overlays Kt/Ds
constexpr int QS_OFF = 0;
constexpr int KT_OFF = QS_OFF + TILE_T * QP;          // 4352
constexpr int DS_OFF = KT_OFF + Dn * KP;              // +8320
constexpr int S_OFF  = DS_OFF + TILE_T * DP;          // +8448
constexpr int SMEM_FLOATS = S_OFF + TILE_T * SPITCH;  // +33280 = 54400
constexpr int SMEM_BYTES  = SMEM_FLOATS * 4;          // 217600 B

extern __shared__ float smem[];

// ---------- f32x2 helpers (PTX-only on sm_10x) ----------
__device__ __forceinline__ ull pk2(float lo, float hi) {
    ull r; asm("mov.b64 %0, {%1,%2};" : "=l"(r) : "f"(lo), "f"(hi)); return r;
}
__device__ __forceinline__ ull dup2(float v) { return pk2(v, v); }
__device__ __forceinline__ void un2(ull v, float& a, float& b) {
    asm("mov.b64 {%0,%1}, %2;" : "=f"(a), "=f"(b) : "l"(v));
}
__device__ __forceinline__ ull f2fma(ull a, ull b, ull c) {
    ull d; asm("fma.rn.f32x2 %0, %1, %2, %3;" : "=l"(d) : "l"(a), "l"(b), "l"(c)); return d;
}
__device__ __forceinline__ ull f2add(ull a, ull b) {
    ull d; asm("add.rn.f32x2 %0, %1, %2;" : "=l"(d) : "l"(a), "l"(b)); return d;
}

__global__ __launch_bounds__(NTHREADS, 1)
void msmha_kernel(const float* __restrict__ qg,
                  const float* __restrict__ kg,
                  const float* __restrict__ vg,
                  const float* __restrict__ dtm,
                  const float* __restrict__ w1g,   // (H,2,16)
                  const float* __restrict__ b1g,   // (H,16)
                  const float* __restrict__ w2g,   // (H,16,1)
                  const float* __restrict__ b2g,   // (H,1)
                  float* __restrict__ outg)        // (B,T,H*Dn)
{
    const int tt  = blockIdx.x;            // T tile 0..7
    const int bh  = blockIdx.y;            // 0..63
    const int b   = bh >> 4;
    const int h   = bh & 15;
    const int t0  = tt * TILE_T;
    const int tid = threadIdx.x;
    const int wid = tid >> 5;              // 0..15
    const int lane = tid & 31;

    float* Qs = smem + QS_OFF;
    float* Kt = smem + KT_OFF;
    float* Ds = smem + DS_OFF;
    float* S  = smem + S_OFF;
    float* Vs = Kt;                        // overlay for phase 3

    // ---- per-head MLP weights as packed scalar pairs (64 regs) ----
    ull w1d2[8], w1x2[8], b12[8], w2h2[8];
    {
        const float* W1 = w1g + h * 2 * HIDn;
        const float* B1 = b1g + h * HIDn;
        const float* W2 = w2g + h * HIDn;
#pragma unroll
        for (int jp = 0; jp < 8; ++jp) {
            w1d2[jp] = pk2(W1[2*jp],        W1[2*jp+1]);
            w1x2[jp] = pk2(W1[HIDn+2*jp],   W1[HIDn+2*jp+1]);
            b12[jp]  = pk2(B1[2*jp],        B1[2*jp+1]);
            w2h2[jp] = pk2(0.5f*W2[2*jp],   0.5f*W2[2*jp+1]);  // fold relu=0.5*(h+|h|)
        }
    }
    const float bias2 = b2g[h];

    // ---- Q tile, prescaled by 1/8 ----
    {
        const float4* src = reinterpret_cast<const float4*>(qg + ((long)bh * Tn + t0) * Dn);
#pragma unroll
        for (int it = 0; it < 2; ++it) {
            int i = tid + NTHREADS * it;
            int row = i >> 4, c4 = i & 15;
            float4 v = src[row * 16 + c4];
            v.x *= 0.125f; v.y *= 0.125f; v.z *= 0.125f; v.w *= 0.125f;
            *reinterpret_cast<float4*>(Qs + row * QP + 4*c4) = v;
        }
    }

    // ============ Phase 1: scores (QK dot + MLP), m-chunks of 128 ============
    const int r0 = 4 * wid;       // warp owns rows r0..r0+3

    for (int mc = 0; mc < Mn / MCH; ++mc) {
        const int m0 = mc * MCH;
        // Kt: transposed K chunk [d][m]; conflict-free STS (lanes->consecutive m)
#pragma unroll
        for (int it = 0; it < 4; ++it) {
            int idx = tid + NTHREADS * it;
            int d4 = idx >> 7, m = idx & 127;
            float4 kv = *reinterpret_cast<const float4*>(kg + ((long)bh * Mn + m0 + m) * Dn + 4*d4);
            Kt[(4*d4+0) * KP + m] = kv.x;
            Kt[(4*d4+1) * KP + m] = kv.y;
            Kt[(4*d4+2) * KP + m] = kv.z;
            Kt[(4*d4+3) * KP + m] = kv.w;
        }
        // D chunk [t][m]
#pragma unroll
        for (int it = 0; it < 4; ++it) {
            int idx = tid + NTHREADS * it;
            int rr = idx >> 5, c4 = idx & 31;
            float4 dv = *reinterpret_cast<const float4*>(dtm + ((long)b * Tn + t0 + rr) * Mn + m0 + 4*c4);
            *reinterpret_cast<float4*>(Ds + rr * DP + 4*c4) = dv;
        }
        __syncthreads();

        // dot: 4 rows x 2 m-pairs per thread, packed over (m, m+1)
        ull acc[4][2];
#pragma unroll
        for (int i = 0; i < 4; ++i) { acc[i][0] = 0ull; acc[i][1] = 0ull; }

        const float4* Qs4 = reinterpret_cast<const float4*>(Qs);
#pragma unroll 4
        for (int d4 = 0; d4 < 16; ++d4) {
            float4 qv[4];
#pragma unroll
            for (int i = 0; i < 4; ++i) qv[i] = Qs4[(r0 + i) * (QP/4) + d4];
#pragma unroll
            for (int dd = 0; dd < 4; ++dd) {
                const int d = 4*d4 + dd;
                ull ka = *reinterpret_cast<const ull*>(Kt + d * KP + 2*lane);
                ull kb = *reinterpret_cast<const ull*>(Kt + d * KP + 64 + 2*lane);
#pragma unroll
                for (int i = 0; i < 4; ++i) {
                    float q = reinterpret_cast<const float*>(&qv[i])[dd];
                    ull qd = dup2(q);
                    acc[i][0] = f2fma(qd, ka, acc[i][0]);
                    acc[i][1] = f2fma(qd, kb, acc[i][1]);
                }
            }
        }

        // MLP over hidden-pairs; relu via h + |h| with folded 0.5*w2
#pragma unroll
        for (int i = 0; i < 4; ++i) {
            const int row = r0 + i;
#pragma unroll
            for (int p = 0; p < 2; ++p) {
                const int mloc = 2*lane + 64*p;
                float da, db; un2(acc[i][p], da, db);
                ull D2 = *reinterpret_cast<const ull*>(Ds + row * DP + mloc);
                float Da, Db; un2(D2, Da, Db);
                float out2[2];
#pragma unroll
                for (int sc = 0; sc < 2; ++sc) {
                    ull dd2 = dup2(sc ? db : da);
                    ull DD2 = dup2(sc ? Db : Da);
                    ull s2 = 0ull;
#pragma unroll
                    for (int jp = 0; jp < 8; ++jp) {
                        ull base = f2fma(DD2, w1x2[jp], b12[jp]);
                        ull hh   = f2fma(dd2, w1d2[jp], base);
                        ull rr2  = f2add(hh, hh & 0x7FFFFFFF7FFFFFFFull);
                        s2 = f2fma(rr2, w2h2[jp], s2);
                    }
                    float slo, shi; un2(s2, slo, shi);
                    out2[sc] = slo + shi + bias2;
                }
                *reinterpret_cast<float2*>(S + row * SPITCH + m0 + mloc) =
                    make_float2(out2[0], out2[1]);
            }
        }
        __syncthreads();
    }

    // ============ Phase 2: softmax with FMA-based exp2 ============
    const int r  = tid >> 3;     // 0..63
    const int l8 = tid & 7;      // 0..7
    float* Sr = S + r * SPITCH;

    float mx = -1e30f;
#pragma unroll 8
    for (int i = 0; i < 32; ++i) {
        float2 v = *reinterpret_cast<const float2*>(Sr + 2*(l8 + 8*i));
        mx = fmaxf(mx, fmaxf(v.x, v.y));
    }
#pragma unroll
    for (int o = 4; o; o >>= 1)
        mx = fmaxf(mx, __shfl_xor_sync(0xffffffffu, mx, o));

    const ull L2E2  = dup2(1.44269504f);
    const ull MAG2  = dup2(12582912.0f);
    const ull NMAG2 = dup2(-12582912.0f);
    const ull NONE2 = dup2(-1.0f);
    const ull ONE2  = dup2(1.0f);
    const ull TC1   = dup2(0.69314718056f);
    const ull TC2   = dup2(0.240226507f);
    const ull TC3   = dup2(0.0555041087f);
    const ull TC4   = dup2(0.00961812911f);
    const ull TC5   = dup2(0.00133335581f);
    const ull CM2   = dup2(-mx * 1.44269504f);

    float sum = 0.f;
#pragma unroll 4
    for (int i = 0; i < 32; ++i) {
        float* sp = Sr + 2*(l8 + 8*i);
        ull x2  = *reinterpret_cast<const ull*>(sp);
        ull a2  = f2fma(x2, L2E2, CM2);        // t = (x-mx)*log2e
        ull fr2 = f2add(a2, MAG2);             // round-to-int magic
        ull nf2 = f2add(fr2, NMAG2);           // n as float
        ull ff2 = f2fma(nf2, NONE2, a2);       // f = t - n  in [-0.5,0.5]
        ull p2  = f2fma(TC5, ff2, TC4);        // 2^f Taylor-5
        p2 = f2fma(p2, ff2, TC3);
        p2 = f2fma(p2, ff2, TC2);
        p2 = f2fma(p2, ff2, TC1);
        p2 = f2fma(p2, ff2, ONE2);
        float frl, frh, pl, ph;
        un2(fr2, frl, frh); un2(p2, pl, ph);
        // exponent insert: bits(fr)<<23 == n<<23 (magic low 9 bits are 0)
        float yl = __int_as_float(__float_as_int(pl) + (__float_as_int(frl) << 23));
        float yh = __int_as_float(__float_as_int(ph) + (__float_as_int(frh) << 23));
        *reinterpret_cast<float2*>(sp) = make_float2(yl, yh);
        sum += yl + yh;
    }
#pragma unroll
    for (int o = 4; o; o >>= 1)
        sum += __shfl_xor_sync(0xffffffffu, sum, o);
    const float inv = 1.0f / sum;
    __syncthreads();

    // ============ Phase 3: O = P @ V, packed over d-pairs ============
    ull o2[4] = {0ull, 0ull, 0ull, 0ull};

    for (int mc = 0; mc < Mn / MCH; ++mc) {
        const int m0 = mc * MCH;
#pragma unroll
        for (int it = 0; it < 4; ++it) {
            int idx = tid + NTHREADS * it;
            int row = idx >> 4, c4 = idx & 15;
            float4 vv = *reinterpret_cast<const float4*>(vg + ((long)bh * Mn + m0 + row) * Dn + 4*c4);
            *reinterpret_cast<float4*>(Vs + row * VP + 4*c4) = vv;
        }
        __syncthreads();

        const float* Sp = S + r * SPITCH + m0;
#pragma unroll 8
        for (int mm = 0; mm < MCH; ++mm) {
            float p = Sp[mm];
            ull pd = dup2(p);
            const ull* vrow = reinterpret_cast<const ull*>(Vs + mm * VP);
            o2[0] = f2fma(pd, vrow[2*l8],      o2[0]);   // d = 4*l8 .. +1
            o2[1] = f2fma(pd, vrow[2*l8 + 1],  o2[1]);   // d = 4*l8+2 ..
            o2[2] = f2fma(pd, vrow[16 + 2*l8], o2[2]);   // d = 32+4*l8 ..
            o2[3] = f2fma(pd, vrow[16 + 2*l8 + 1], o2[3]);
        }
        __syncthreads();
    }

    // epilogue: normalize + store
    {
        float ox[8];
        un2(o2[0], ox[0], ox[1]); un2(o2[1], ox[2], ox[3]);
        un2(o2[2], ox[4], ox[5]); un2(o2[3], ox[6], ox[7]);
        float* op = outg + ((long)b * Tn + t0 + r) * (Hn * Dn) + h * Dn;
        float4 ra = {ox[0]*inv, ox[1]*inv, ox[2]*inv, ox[3]*inv};
        float4 rb = {ox[4]*inv, ox[5]*inv, ox[6]*inv, ox[7]*inv};
        *reinterpret_cast<float4*>(op + 4*l8)      = ra;
        *reinterpret_cast<float4*>(op + 32 + 4*l8) = rb;
    }
}

extern "C" void kernel_launch(void* const* d_in, const int* in_sizes, int n_in,
                              void* d_out, int out_size)
{
    const float* q   = (const float*)d_in[0];
    const float* k   = (const float*)d_in[1];
    const float* v   = (const float*)d_in[2];
    const float* dtm = (const float*)d_in[3];
    const float* w1  = (const float*)d_in[4];
    const float* b1  = (const float*)d_in[5];
    const float* w2  = (const float*)d_in[6];
    const float* b2  = (const float*)d_in[7];
    float* out = (float*)d_out;

    cudaFuncSetAttribute(msmha_kernel,
                         cudaFuncAttributeMaxDynamicSharedMemorySize, SMEM_BYTES);

    dim3 grid(Tn / TILE_T, Bn * Hn);   // (8, 64)
    msmha_kernel<<<grid, NTHREADS, SMEM_BYTES>>>(q, k, v, dtm, w1, b1, w2, b2, out);
}

// round 6
// speedup vs baseline: 1.4046x; 1.3087x over previous
#include <cuda_runtime.h>
#include <cuda_bf16.h>

// Problem shapes (fixed)
#define Bn   4
#define Hn   16
#define Tn   512
#define Mn   512
#define Dn   64
#define HIDn 16

typedef unsigned long long ull;

constexpr int NTH     = 512;
constexpr int TILE_T  = 64;
constexpr int MCH     = 128;     // m-chunk (4 chunks)
constexpr int SPITCH  = 520;     // score row pitch (words)
constexpr int QDP     = 132;     // Q-dup row pitch: 128 payload words + 4 pad
constexpr int KTP     = 132;     // Kt pitch over m (words)
constexpr int VP      = 68;      // V row pitch (words)
constexpr int PPITCH  = 68;      // partial row pitch (words)

// word offsets in dyn smem
constexpr int S_OFF   = 0;                        // 64*520 = 33280
constexpr int QD_OFF  = TILE_T * SPITCH;          // 33280 (Q-dup, 64*132 = 8448)
constexpr int KT_OFF  = QD_OFF + TILE_T * QDP;    // 41728 (Kt, 64*132 = 8448)
constexpr int VS_OFF  = QD_OFF;                   // V overlays Qd in phase 3
constexpr int PP_OFF  = QD_OFF;                   // partials overlay Vs/Kt after barrier
constexpr int PP_SLICE = TILE_T * PPITCH;         // 4352 words per m-split slice
constexpr int SMEM_WORDS = PP_OFF + 4 * PP_SLICE; // 50688
constexpr int SMEM_BYTES = SMEM_WORDS * 4;        // 202752 B

extern __shared__ float smem[];

// ---------- f32x2 helpers ----------
__device__ __forceinline__ ull pk2(float lo, float hi) {
    ull r; asm("mov.b64 %0, {%1,%2};" : "=l"(r) : "f"(lo), "f"(hi)); return r;
}
__device__ __forceinline__ ull dup2(float v) { return pk2(v, v); }
__device__ __forceinline__ void un2(ull v, float& a, float& b) {
    asm("mov.b64 {%0,%1}, %2;" : "=f"(a), "=f"(b) : "l"(v));
}
__device__ __forceinline__ ull f2fma(ull a, ull b, ull c) {
    ull d; asm("fma.rn.f32x2 %0, %1, %2, %3;" : "=l"(d) : "l"(a), "l"(b), "l"(c)); return d;
}
__device__ __forceinline__ ull f2add(ull a, ull b) {
    ull d; asm("add.rn.f32x2 %0, %1, %2;" : "=l"(d) : "l"(a), "l"(b)); return d;
}

__global__ __launch_bounds__(NTH, 1)
void msmha_kernel(const float* __restrict__ qg,
                  const float* __restrict__ kg,
                  const float* __restrict__ vg,
                  const float* __restrict__ dtm,
                  const float* __restrict__ w1g,
                  const float* __restrict__ b1g,
                  const float* __restrict__ w2g,
                  const float* __restrict__ b2g,
                  float* __restrict__ outg)
{
    const int tt   = blockIdx.x;
    const int bh   = blockIdx.y;
    const int b    = bh >> 4;
    const int h    = bh & 15;
    const int t0   = tt * TILE_T;
    const int tid  = threadIdx.x;
    const int wid  = tid >> 5;
    const int lane = tid & 31;
    const int lr   = lane >> 2;   // 0..7
    const int lm   = lane & 3;    // 0..3

    float* S  = smem + S_OFF;

    // ---- per-head MLP weights packed over hidden pairs ----
    ull w1d2[8], w1x2[8], b12[8], w2h2[8];
    {
        const float* W1 = w1g + h * 2 * HIDn;
        const float* B1 = b1g + h * HIDn;
        const float* W2 = w2g + h * HIDn;
#pragma unroll
        for (int jp = 0; jp < 8; ++jp) {
            w1d2[jp] = pk2(W1[2*jp],      W1[2*jp+1]);
            w1x2[jp] = pk2(W1[HIDn+2*jp], W1[HIDn+2*jp+1]);
            b12[jp]  = pk2(B1[2*jp],      B1[2*jp+1]);
            w2h2[jp] = pk2(0.5f*W2[2*jp], 0.5f*W2[2*jp+1]);   // relu = 0.5*(h+|h|)
        }
    }
    const float bias2 = b2g[h];

    // ---- Q tile as DUPLICATED f32x2 pairs, prescaled 1/8 ----
    // element d of row lives at words row*QDP + 2*d .. 2*d+1 (duplicated)
    {
        float* Qd = smem + QD_OFF;
#pragma unroll
        for (int it = 0; it < 2; ++it) {
            int i = tid + NTH * it;           // 0..1023
            int row = i >> 4, c4 = i & 15;
            float4 v = *reinterpret_cast<const float4*>(qg + ((long)bh*Tn + t0 + row)*Dn + 4*c4);
            float4 a = {0.125f*v.x, 0.125f*v.x, 0.125f*v.y, 0.125f*v.y};
            float4 c = {0.125f*v.z, 0.125f*v.z, 0.125f*v.w, 0.125f*v.w};
            *reinterpret_cast<float4*>(Qd + row*QDP + 8*c4)     = a;
            *reinterpret_cast<float4*>(Qd + row*QDP + 8*c4 + 4) = c;
        }
    }

    // ============ Phase 1: scores ============
    // warp tile: 32 rows x 16 m.  warp: rw = wid>>3 (row half), mw = wid&7 (m group)
    const int rw     = wid >> 3;
    const int mw     = wid & 7;
    const int rbase  = rw * 32 + lr;          // rows rbase + 8*i
    const int mbase  = mw * 16 + 4 * lm;      // 4 m (2 ull) per thread

    for (int mc = 0; mc < Mn / MCH; ++mc) {
        const int m0 = mc * MCH;

        // Kt loader: [d][m], conflict-free STS (lanes -> consecutive m)
        {
            float* Kt = smem + KT_OFF;
#pragma unroll
            for (int it = 0; it < 4; ++it) {
                int idx = tid + NTH * it;          // 0..2047
                int m = idx & 127, d4 = idx >> 7;  // d4 0..15
                float4 kv = *reinterpret_cast<const float4*>(kg + ((long)bh*Mn + m0 + m)*Dn + 4*d4);
                Kt[(4*d4+0)*KTP + m] = kv.x;
                Kt[(4*d4+1)*KTP + m] = kv.y;
                Kt[(4*d4+2)*KTP + m] = kv.z;
                Kt[(4*d4+3)*KTP + m] = kv.w;
            }
        }
        __syncthreads();

        ull acc[4][2];
#pragma unroll
        for (int i = 0; i < 4; ++i) { acc[i][0] = 0ull; acc[i][1] = 0ull; }

        const float* Qd = smem + QD_OFF;
        const float* Kt = smem + KT_OFF;
#pragma unroll 8
        for (int dp = 0; dp < Dn; dp += 2) {
            ulonglong2 qq[4];
#pragma unroll
            for (int i = 0; i < 4; ++i)
                qq[i] = *reinterpret_cast<const ulonglong2*>(Qd + (rbase + 8*i)*QDP + 2*dp);
#pragma unroll
            for (int sub = 0; sub < 2; ++sub) {
                ulonglong2 kk = *reinterpret_cast<const ulonglong2*>(Kt + (dp+sub)*KTP + mbase);
#pragma unroll
                for (int i = 0; i < 4; ++i) {
                    ull qd = sub ? qq[i].y : qq[i].x;
                    acc[i][0] = f2fma(qd, kk.x, acc[i][0]);
                    acc[i][1] = f2fma(qd, kk.y, acc[i][1]);
                }
            }
        }

        // D prefetch (L2-resident), then MLP, then S store
        float4 Dv[4];
#pragma unroll
        for (int i = 0; i < 4; ++i)
            Dv[i] = *reinterpret_cast<const float4*>(dtm + ((long)b*Tn + t0 + rbase + 8*i)*Mn + m0 + mbase);

#pragma unroll
        for (int i = 0; i < 4; ++i) {
            const int row = rbase + 8*i;
            float o4[4];
#pragma unroll
            for (int u = 0; u < 2; ++u) {
                float da, db; un2(acc[i][u], da, db);
                const float D0 = u ? Dv[i].z : Dv[i].x;
                const float D1 = u ? Dv[i].w : Dv[i].y;
#pragma unroll
                for (int sc = 0; sc < 2; ++sc) {
                    ull dd2 = dup2(sc ? db : da);
                    ull DD2 = dup2(sc ? D1 : D0);
                    ull s2 = 0ull;
#pragma unroll
                    for (int jp = 0; jp < 8; ++jp) {
                        ull base = f2fma(DD2, w1x2[jp], b12[jp]);
                        ull hh   = f2fma(dd2, w1d2[jp], base);
                        ull rr2  = f2add(hh, hh & 0x7FFFFFFF7FFFFFFFull);
                        s2 = f2fma(rr2, w2h2[jp], s2);
                    }
                    float slo, shi; un2(s2, slo, shi);
                    o4[2*u + sc] = slo + shi + bias2;
                }
            }
            *reinterpret_cast<float4*>(S + row*SPITCH + m0 + mbase) =
                make_float4(o4[0], o4[1], o4[2], o4[3]);
        }
        __syncthreads();
    }

    // ============ Phase 2: softmax (FMA-based exp2) ============
    const int r  = tid >> 3;
    const int l8 = tid & 7;
    float* Sr = S + r * SPITCH;

    float mx = -1e30f;
#pragma unroll 8
    for (int i = 0; i < 32; ++i) {
        float2 v = *reinterpret_cast<const float2*>(Sr + 2*(l8 + 8*i));
        mx = fmaxf(mx, fmaxf(v.x, v.y));
    }
#pragma unroll
    for (int o = 4; o; o >>= 1)
        mx = fmaxf(mx, __shfl_xor_sync(0xffffffffu, mx, o));

    const ull L2E2  = dup2(1.44269504f);
    const ull MAG2  = dup2(12582912.0f);
    const ull NMAG2 = dup2(-12582912.0f);
    const ull NONE2 = dup2(-1.0f);
    const ull ONE2  = dup2(1.0f);
    const ull TC1   = dup2(0.69314718056f);
    const ull TC2   = dup2(0.240226507f);
    const ull TC3   = dup2(0.0555041087f);
    const ull TC4   = dup2(0.00961812911f);
    const ull TC5   = dup2(0.00133335581f);
    const ull CM2   = dup2(-mx * 1.44269504f);

    float sum = 0.f;
#pragma unroll 4
    for (int i = 0; i < 32; ++i) {
        float* sp = Sr + 2*(l8 + 8*i);
        ull x2  = *reinterpret_cast<const ull*>(sp);
        ull a2  = f2fma(x2, L2E2, CM2);
        ull fr2 = f2add(a2, MAG2);
        ull nf2 = f2add(fr2, NMAG2);
        ull ff2 = f2fma(nf2, NONE2, a2);
        ull p2  = f2fma(TC5, ff2, TC4);
        p2 = f2fma(p2, ff2, TC3);
        p2 = f2fma(p2, ff2, TC2);
        p2 = f2fma(p2, ff2, TC1);
        p2 = f2fma(p2, ff2, ONE2);
        float frl, frh, pl, ph;
        un2(fr2, frl, frh); un2(p2, pl, ph);
        float yl = __int_as_float(__float_as_int(pl) + (__float_as_int(frl) << 23));
        float yh = __int_as_float(__float_as_int(ph) + (__float_as_int(frh) << 23));
        *reinterpret_cast<float2*>(sp) = make_float2(yl, yh);
        sum += yl + yh;
    }
#pragma unroll
    for (int o = 4; o; o >>= 1)
        sum += __shfl_xor_sync(0xffffffffu, sum, o);
    const float inv = 1.0f / sum;
    __syncthreads();

    // ============ Phase 3: O = P @ V ============
    // warp: rw3 = wid&1 (row half), dw = (wid>>1)&1 (d half), mw3 = wid>>2 (m split 0..3)
    const int rw3   = wid & 1;
    const int dw    = (wid >> 1) & 1;
    const int mw3   = wid >> 2;
    const int r3b   = rw3 * 32 + lr;          // rows r3b + 8*i
    const int d3a   = dw * 32 + 4 * lm;       // first float4 of d-tile

    ull o2[4][4];
#pragma unroll
    for (int i = 0; i < 4; ++i)
#pragma unroll
        for (int u = 0; u < 4; ++u) o2[i][u] = 0ull;

    for (int mc = 0; mc < Mn / MCH; ++mc) {
        const int m0 = mc * MCH;
        // V loader
        {
            float* Vs = smem + VS_OFF;
#pragma unroll
            for (int it = 0; it < 4; ++it) {
                int idx = tid + NTH * it;          // 0..2047
                int row = idx >> 4, c4 = idx & 15;
                float4 vv = *reinterpret_cast<const float4*>(vg + ((long)bh*Mn + m0 + row)*Dn + 4*c4);
                *reinterpret_cast<float4*>(Vs + row*VP + 4*c4) = vv;
            }
        }
        __syncthreads();

        const float* Vs = smem + VS_OFF;
        const int ms = m0 + mw3 * 32;
#pragma unroll 2
        for (int s4 = 0; s4 < 32; s4 += 4) {
            float4 sp[4];
#pragma unroll
            for (int i = 0; i < 4; ++i)
                sp[i] = *reinterpret_cast<const float4*>(S + (r3b + 8*i)*SPITCH + ms + s4);
#pragma unroll
            for (int t = 0; t < 4; ++t) {
                const int mm = s4 + t;   // local within slice
                ulonglong2 va = *reinterpret_cast<const ulonglong2*>(Vs + (mw3*32 + mm)*VP + d3a);
                ulonglong2 vb = *reinterpret_cast<const ulonglong2*>(Vs + (mw3*32 + mm)*VP + d3a + 16);
#pragma unroll
                for (int i = 0; i < 4; ++i) {
                    float p = (t == 0) ? sp[i].x : (t == 1) ? sp[i].y : (t == 2) ? sp[i].z : sp[i].w;
                    ull pd = dup2(p);
                    o2[i][0] = f2fma(pd, va.x, o2[i][0]);
                    o2[i][1] = f2fma(pd, va.y, o2[i][1]);
                    o2[i][2] = f2fma(pd, vb.x, o2[i][2]);
                    o2[i][3] = f2fma(pd, vb.y, o2[i][3]);
                }
            }
        }
        __syncthreads();
    }

    // partial store (overlays Vs/Kt, safe after barrier)
    {
        float* Pp = smem + PP_OFF + mw3 * PP_SLICE;
#pragma unroll
        for (int i = 0; i < 4; ++i) {
            const int row = r3b + 8*i;
            float a0, a1, a2v, a3, b0, b1v, b2v, b3;
            un2(o2[i][0], a0, a1); un2(o2[i][1], a2v, a3);
            un2(o2[i][2], b0, b1v); un2(o2[i][3], b2v, b3);
            *reinterpret_cast<float4*>(Pp + row*PPITCH + d3a)      = make_float4(a0, a1, a2v, a3);
            *reinterpret_cast<float4*>(Pp + row*PPITCH + d3a + 16) = make_float4(b0, b1v, b2v, b3);
        }
    }
    __syncthreads();

    // cross-slice reduce + normalize + store  (mapping matches phase 2: (r, l8) -> inv)
    {
        const float* Pp = smem + PP_OFF;
        float4 s0 = make_float4(0.f, 0.f, 0.f, 0.f);
        float4 s1 = make_float4(0.f, 0.f, 0.f, 0.f);
#pragma unroll
        for (int s = 0; s < 4; ++s) {
            float4 p0 = *reinterpret_cast<const float4*>(Pp + s*PP_SLICE + r*PPITCH + 4*l8);
            float4 p1 = *reinterpret_cast<const float4*>(Pp + s*PP_SLICE + r*PPITCH + 32 + 4*l8);
            s0.x += p0.x; s0.y += p0.y; s0.z += p0.z; s0.w += p0.w;
            s1.x += p1.x; s1.y += p1.y; s1.z += p1.z; s1.w += p1.w;
        }
        float* op = outg + ((long)b*Tn + t0 + r) * (Hn*Dn) + h*Dn;
        *reinterpret_cast<float4*>(op + 4*l8)      = make_float4(s0.x*inv, s0.y*inv, s0.z*inv, s0.w*inv);
        *reinterpret_cast<float4*>(op + 32 + 4*l8) = make_float4(s1.x*inv, s1.y*inv, s1.z*inv, s1.w*inv);
    }
}

extern "C" void kernel_launch(void* const* d_in, const int* in_sizes, int n_in,
                              void* d_out, int out_size)
{
    const float* q   = (const float*)d_in[0];
    const float* k   = (const float*)d_in[1];
    const float* v   = (const float*)d_in[2];
    const float* dtm = (const float*)d_in[3];
    const float* w1  = (const float*)d_in[4];
    const float* b1  = (const float*)d_in[5];
    const float* w2  = (const float*)d_in[6];
    const float* b2  = (const float*)d_in[7];
    float* out = (float*)d_out;

    cudaFuncSetAttribute(msmha_kernel,
                         cudaFuncAttributeMaxDynamicSharedMemorySize, SMEM_BYTES);

    dim3 grid(Tn / TILE_T, Bn * Hn);   // (8, 64)
    msmha_kernel<<<grid, NTH, SMEM_BYTES>>>(q, k, v, dtm, w1, b1, w2, b2, out);
}

// round 7
// speedup vs baseline: 1.4659x; 1.0436x over previous
#include <cuda_runtime.h>
#include <cuda_bf16.h>

// Problem shapes (fixed)
#define Bn   4
#define Hn   16
#define Tn   512
#define Mn   512
#define Dn   64
#define HIDn 16

typedef unsigned long long ull;

constexpr int NTH     = 512;
constexpr int TILE_T  = 64;
constexpr int MCH     = 128;     // m-chunk (4 chunks)
constexpr int SPITCH  = 520;     // score row pitch (words)
constexpr int QDP     = 132;     // Q-dup row pitch: 128 payload words + 4 pad
constexpr int KTP     = 132;     // Kt pitch over m (words)
constexpr int VP      = 68;      // V row pitch (words)
constexpr int PPITCH  = 68;      // partial row pitch (words)

// word offsets in dyn smem
constexpr int S_OFF   = 0;                        // 64*520 = 33280
constexpr int QD_OFF  = TILE_T * SPITCH;          // 33280 (Q-dup, 64*132)
constexpr int KT_OFF  = QD_OFF + TILE_T * QDP;    // 41728 (Kt, 64*132)
constexpr int VS_OFF  = QD_OFF;                   // V overlays Qd in phase 3
constexpr int PP_OFF  = QD_OFF;                   // partials overlay Vs/Kt after barrier
constexpr int PP_SLICE = TILE_T * PPITCH;         // 4352 words per m-split slice
constexpr int PSUM_OFF = PP_OFF + 4 * PP_SLICE;   // 50688 (8 x 64 row sums)
constexpr int SMEM_WORDS = PSUM_OFF + 512;        // 51200
constexpr int SMEM_BYTES = SMEM_WORDS * 4;        // 204800 B

extern __shared__ float smem[];

// ---------- f32x2 helpers ----------
__device__ __forceinline__ ull pk2(float lo, float hi) {
    ull r; asm("mov.b64 %0, {%1,%2};" : "=l"(r) : "f"(lo), "f"(hi)); return r;
}
__device__ __forceinline__ ull dup2(float v) { return pk2(v, v); }
__device__ __forceinline__ void un2(ull v, float& a, float& b) {
    asm("mov.b64 {%0,%1}, %2;" : "=f"(a), "=f"(b) : "l"(v));
}
__device__ __forceinline__ ull f2fma(ull a, ull b, ull c) {
    ull d; asm("fma.rn.f32x2 %0, %1, %2, %3;" : "=l"(d) : "l"(a), "l"(b), "l"(c)); return d;
}
__device__ __forceinline__ ull f2add(ull a, ull b) {
    ull d; asm("add.rn.f32x2 %0, %1, %2;" : "=l"(d) : "l"(a), "l"(b)); return d;
}

// packed exp2 of (s * log2e + C), C = (bias2 - 20) * log2e folded by caller.
// valid for argument in [-70, 40]; result = 2^arg.
__device__ __forceinline__ ull exp2p(ull s2, ull L2E2, ull C2) {
    const ull MAG2  = dup2(12582912.0f);    // 1.5 * 2^23
    const ull NONE2 = dup2(-1.0f);
    const ull ONE2  = dup2(1.0f);
    const ull TC1   = dup2(0.69314718056f);
    const ull TC2   = dup2(0.240226507f);
    const ull TC3   = dup2(0.0555041087f);
    const ull TC4   = dup2(0.00961812911f);
    const ull TC5   = dup2(0.00133335581f);
    ull a2  = f2fma(s2, L2E2, C2);
    ull fr2 = f2add(a2, MAG2);
    ull nf2 = f2fma(MAG2, NONE2, fr2);      // n as float
    ull ff2 = f2fma(nf2, NONE2, a2);        // f in [-0.5, 0.5]
    ull p2  = f2fma(TC5, ff2, TC4);
    p2 = f2fma(p2, ff2, TC3);
    p2 = f2fma(p2, ff2, TC2);
    p2 = f2fma(p2, ff2, TC1);
    p2 = f2fma(p2, ff2, ONE2);
    float frl, frh, pl, ph;
    un2(fr2, frl, frh); un2(p2, pl, ph);
    float yl = __int_as_float(__float_as_int(pl) + (__float_as_int(frl) << 23));
    float yh = __int_as_float(__float_as_int(ph) + (__float_as_int(frh) << 23));
    return pk2(yl, yh);
}

__global__ __launch_bounds__(NTH, 1)
void msmha_kernel(const float* __restrict__ qg,
                  const float* __restrict__ kg,
                  const float* __restrict__ vg,
                  const float* __restrict__ dtm,
                  const float* __restrict__ w1g,
                  const float* __restrict__ b1g,
                  const float* __restrict__ w2g,
                  const float* __restrict__ b2g,
                  float* __restrict__ outg)
{
    const int tt   = blockIdx.x;
    const int bh   = blockIdx.y;
    const int b    = bh >> 4;
    const int h    = bh & 15;
    const int t0   = tt * TILE_T;
    const int tid  = threadIdx.x;
    const int wid  = tid >> 5;
    const int lane = tid & 31;
    const int lr   = lane >> 2;   // 0..7
    const int lm   = lane & 3;    // 0..3

    float* S  = smem + S_OFF;

    // ---- per-head MLP weights packed over hidden pairs ----
    ull w1d2[8], w1x2[8], b12[8], w2h2[8];
    {
        const float* W1 = w1g + h * 2 * HIDn;
        const float* B1 = b1g + h * HIDn;
        const float* W2 = w2g + h * HIDn;
#pragma unroll
        for (int jp = 0; jp < 8; ++jp) {
            w1d2[jp] = pk2(W1[2*jp],      W1[2*jp+1]);
            w1x2[jp] = pk2(W1[HIDn+2*jp], W1[HIDn+2*jp+1]);
            b12[jp]  = pk2(B1[2*jp],      B1[2*jp+1]);
            w2h2[jp] = pk2(0.5f*W2[2*jp], 0.5f*W2[2*jp+1]);   // relu = 0.5*(h+|h|)
        }
    }
    // exp constants: P = exp2((s + bias2 - 20) * log2e)
    const ull L2E2 = dup2(1.44269504f);
    const ull CEX2 = dup2((b2g[h] - 20.0f) * 1.44269504f);

    // ---- Q tile as DUPLICATED f32x2 pairs, prescaled 1/8 ----
    {
        float* Qd = smem + QD_OFF;
#pragma unroll
        for (int it = 0; it < 2; ++it) {
            int i = tid + NTH * it;           // 0..1023
            int row = i >> 4, c4 = i & 15;
            float4 v = *reinterpret_cast<const float4*>(qg + ((long)bh*Tn + t0 + row)*Dn + 4*c4);
            float4 a = {0.125f*v.x, 0.125f*v.x, 0.125f*v.y, 0.125f*v.y};
            float4 c = {0.125f*v.z, 0.125f*v.z, 0.125f*v.w, 0.125f*v.w};
            *reinterpret_cast<float4*>(Qd + row*QDP + 8*c4)     = a;
            *reinterpret_cast<float4*>(Qd + row*QDP + 8*c4 + 4) = c;
        }
    }

    // ============ Phase 1: P = exp(mixed score - 20) straight into S ============
    // warp tile: 32 rows x 16 m.  rw = wid>>3 (row half), mw = wid&7 (m group)
    const int rw     = wid >> 3;
    const int mw     = wid & 7;
    const int rbase  = rw * 32 + lr;          // rows rbase + 8*i
    const int mbase  = mw * 16 + 4 * lm;      // 4 m per thread

    float rowsum[4] = {0.f, 0.f, 0.f, 0.f};

    for (int mc = 0; mc < Mn / MCH; ++mc) {
        const int m0 = mc * MCH;

        // Kt loader: [d][m], conflict-free STS
        {
            float* Kt = smem + KT_OFF;
#pragma unroll
            for (int it = 0; it < 4; ++it) {
                int idx = tid + NTH * it;
                int m = idx & 127, d4 = idx >> 7;
                float4 kv = *reinterpret_cast<const float4*>(kg + ((long)bh*Mn + m0 + m)*Dn + 4*d4);
                Kt[(4*d4+0)*KTP + m] = kv.x;
                Kt[(4*d4+1)*KTP + m] = kv.y;
                Kt[(4*d4+2)*KTP + m] = kv.z;
                Kt[(4*d4+3)*KTP + m] = kv.w;
            }
        }
        __syncthreads();

        ull acc[4][2];
#pragma unroll
        for (int i = 0; i < 4; ++i) { acc[i][0] = 0ull; acc[i][1] = 0ull; }

        const float* Qd = smem + QD_OFF;
        const float* Kt = smem + KT_OFF;
#pragma unroll 8
        for (int dp = 0; dp < Dn; dp += 2) {
            ulonglong2 qq[4];
#pragma unroll
            for (int i = 0; i < 4; ++i)
                qq[i] = *reinterpret_cast<const ulonglong2*>(Qd + (rbase + 8*i)*QDP + 2*dp);
#pragma unroll
            for (int sub = 0; sub < 2; ++sub) {
                ulonglong2 kk = *reinterpret_cast<const ulonglong2*>(Kt + (dp+sub)*KTP + mbase);
#pragma unroll
                for (int i = 0; i < 4; ++i) {
                    ull qd = sub ? qq[i].y : qq[i].x;
                    acc[i][0] = f2fma(qd, kk.x, acc[i][0]);
                    acc[i][1] = f2fma(qd, kk.y, acc[i][1]);
                }
            }
        }

        // D prefetch (L2-resident)
        float4 Dv[4];
#pragma unroll
        for (int i = 0; i < 4; ++i)
            Dv[i] = *reinterpret_cast<const float4*>(dtm + ((long)b*Tn + t0 + rbase + 8*i)*Mn + m0 + mbase);

        // MLP + exp -> P, store + rowsum
#pragma unroll
        for (int i = 0; i < 4; ++i) {
            const int row = rbase + 8*i;
            float o4[4];
#pragma unroll
            for (int u = 0; u < 2; ++u) {
                float da, db; un2(acc[i][u], da, db);
                const float D0 = u ? Dv[i].z : Dv[i].x;
                const float D1 = u ? Dv[i].w : Dv[i].y;
#pragma unroll
                for (int sc = 0; sc < 2; ++sc) {
                    ull dd2 = dup2(sc ? db : da);
                    ull DD2 = dup2(sc ? D1 : D0);
                    ull s2 = 0ull;
#pragma unroll
                    for (int jp = 0; jp < 8; ++jp) {
                        ull base = f2fma(DD2, w1x2[jp], b12[jp]);
                        ull hh   = f2fma(dd2, w1d2[jp], base);
                        ull rr2  = f2add(hh, hh & 0x7FFFFFFF7FFFFFFFull);
                        s2 = f2fma(rr2, w2h2[jp], s2);
                    }
                    float slo, shi; un2(s2, slo, shi);
                    o4[2*u + sc] = slo + shi;        // bias2 folded into CEX2
                }
            }
            ull y0 = exp2p(pk2(o4[0], o4[1]), L2E2, CEX2);
            ull y1 = exp2p(pk2(o4[2], o4[3]), L2E2, CEX2);
            float p0, p1, p2v, p3;
            un2(y0, p0, p1); un2(y1, p2v, p3);
            rowsum[i] += (p0 + p1) + (p2v + p3);
            *reinterpret_cast<float4*>(S + row*SPITCH + m0 + mbase) =
                make_float4(p0, p1, p2v, p3);
        }
        __syncthreads();
    }

    // ---- row-sum reduce: over lm lanes (xor 1,2), then Psum[mw][row] ----
    {
#pragma unroll
        for (int i = 0; i < 4; ++i) {
            rowsum[i] += __shfl_xor_sync(0xffffffffu, rowsum[i], 1);
            rowsum[i] += __shfl_xor_sync(0xffffffffu, rowsum[i], 2);
        }
        if (lm == 0) {
            float* Psum = smem + PSUM_OFF;
#pragma unroll
            for (int i = 0; i < 4; ++i)
                Psum[mw * 64 + rbase + 8*i] = rowsum[i];
        }
    }
    __syncthreads();

    // ============ Phase 3: O = P @ V ============
    const int rw3   = wid & 1;
    const int dw    = (wid >> 1) & 1;
    const int mw3   = wid >> 2;
    const int r3b   = rw3 * 32 + lr;
    const int d3a   = dw * 32 + 4 * lm;

    ull o2[4][4];
#pragma unroll
    for (int i = 0; i < 4; ++i)
#pragma unroll
        for (int u = 0; u < 4; ++u) o2[i][u] = 0ull;

    for (int mc = 0; mc < Mn / MCH; ++mc) {
        const int m0 = mc * MCH;
        {
            float* Vs = smem + VS_OFF;
#pragma unroll
            for (int it = 0; it < 4; ++it) {
                int idx = tid + NTH * it;
                int row = idx >> 4, c4 = idx & 15;
                float4 vv = *reinterpret_cast<const float4*>(vg + ((long)bh*Mn + m0 + row)*Dn + 4*c4);
                *reinterpret_cast<float4*>(Vs + row*VP + 4*c4) = vv;
            }
        }
        __syncthreads();

        const float* Vs = smem + VS_OFF;
        const int ms = m0 + mw3 * 32;
#pragma unroll 2
        for (int s4 = 0; s4 < 32; s4 += 4) {
            float4 sp[4];
#pragma unroll
            for (int i = 0; i < 4; ++i)
                sp[i] = *reinterpret_cast<const float4*>(S + (r3b + 8*i)*SPITCH + ms + s4);
#pragma unroll
            for (int t = 0; t < 4; ++t) {
                const int mm = s4 + t;
                ulonglong2 va = *reinterpret_cast<const ulonglong2*>(Vs + (mw3*32 + mm)*VP + d3a);
                ulonglong2 vb = *reinterpret_cast<const ulonglong2*>(Vs + (mw3*32 + mm)*VP + d3a + 16);
#pragma unroll
                for (int i = 0; i < 4; ++i) {
                    float p = (t == 0) ? sp[i].x : (t == 1) ? sp[i].y : (t == 2) ? sp[i].z : sp[i].w;
                    ull pd = dup2(p);
                    o2[i][0] = f2fma(pd, va.x, o2[i][0]);
                    o2[i][1] = f2fma(pd, va.y, o2[i][1]);
                    o2[i][2] = f2fma(pd, vb.x, o2[i][2]);
                    o2[i][3] = f2fma(pd, vb.y, o2[i][3]);
                }
            }
        }
        __syncthreads();
    }

    // partial store (overlays Vs/Kt)
    {
        float* Pp = smem + PP_OFF + mw3 * PP_SLICE;
#pragma unroll
        for (int i = 0; i < 4; ++i) {
            const int row = r3b + 8*i;
            float a0, a1, a2v, a3, b0, b1v, b2v, b3;
            un2(o2[i][0], a0, a1); un2(o2[i][1], a2v, a3);
            un2(o2[i][2], b0, b1v); un2(o2[i][3], b2v, b3);
            *reinterpret_cast<float4*>(Pp + row*PPITCH + d3a)      = make_float4(a0, a1, a2v, a3);
            *reinterpret_cast<float4*>(Pp + row*PPITCH + d3a + 16) = make_float4(b0, b1v, b2v, b3);
        }
    }
    __syncthreads();

    // cross-slice reduce + normalize + store
    {
        const int r  = tid >> 3;
        const int l8 = tid & 7;
        const float* Psum = smem + PSUM_OFF;
        float sum = 0.f;
#pragma unroll
        for (int s = 0; s < 8; ++s) sum += Psum[s * 64 + r];
        const float inv = 1.0f / sum;

        const float* Pp = smem + PP_OFF;
        float4 s0 = make_float4(0.f, 0.f, 0.f, 0.f);
        float4 s1 = make_float4(0.f, 0.f, 0.f, 0.f);
#pragma unroll
        for (int s = 0; s < 4; ++s) {
            float4 p0 = *reinterpret_cast<const float4*>(Pp + s*PP_SLICE + r*PPITCH + 4*l8);
            float4 p1 = *reinterpret_cast<const float4*>(Pp + s*PP_SLICE + r*PPITCH + 32 + 4*l8);
            s0.x += p0.x; s0.y += p0.y; s0.z += p0.z; s0.w += p0.w;
            s1.x += p1.x; s1.y += p1.y; s1.z += p1.z; s1.w += p1.w;
        }
        float* op = outg + ((long)b*Tn + t0 + r) * (Hn*Dn) + h*Dn;
        *reinterpret_cast<float4*>(op + 4*l8)      = make_float4(s0.x*inv, s0.y*inv, s0.z*inv, s0.w*inv);
        *reinterpret_cast<float4*>(op + 32 + 4*l8) = make_float4(s1.x*inv, s1.y*inv, s1.z*inv, s1.w*inv);
    }
}

extern "C" void kernel_launch(void* const* d_in, const int* in_sizes, int n_in,
                              void* d_out, int out_size)
{
    const float* q   = (const float*)d_in[0];
    const float* k   = (const float*)d_in[1];
    const float* v   = (const float*)d_in[2];
    const float* dtm = (const float*)d_in[3];
    const float* w1  = (const float*)d_in[4];
    const float* b1  = (const float*)d_in[5];
    const float* w2  = (const float*)d_in[6];
    const float* b2  = (const float*)d_in[7];
    float* out = (float*)d_out;

    cudaFuncSetAttribute(msmha_kernel,
                         cudaFuncAttributeMaxDynamicSharedMemorySize, SMEM_BYTES);

    dim3 grid(Tn / TILE_T, Bn * Hn);   // (8, 64)
    msmha_kernel<<<grid, NTH, SMEM_BYTES>>>(q, k, v, dtm, w1, b1, w2, b2, out);
}

// round 10
// speedup vs baseline: 2.7665x; 1.8872x over previous
#include <cuda_runtime.h>
#include <cuda_bf16.h>
#include <cstdint>

// Shapes (fixed)
#define Bn   4
#define Hn   16
#define Tn   512
#define Mn   512
#define Dn   64
#define HIDn 16

typedef unsigned long long ull;

constexpr int NTH    = 512;
constexpr int TILE_T = 128;
constexpr int MCH    = 128;
constexpr int NCHUNK = 4;

constexpr int QKP    = 36;   // words/row, Q & K bf16 tiles [128][64]  (144 B)
constexpr int VTP    = 68;   // words/row, Vt bf16 [64][128]           (272 B)
constexpr int OPITCH = 72;   // words/row, O partial smem [128][64] f32

// smem byte offsets
constexpr int SM_QH   = 0;
constexpr int SM_QL   = SM_QH  + TILE_T*QKP*4;     // 18432
constexpr int SM_KH   = SM_QL  + TILE_T*QKP*4;     // 36864
constexpr int SM_KL   = SM_KH  + TILE_T*QKP*4;     // 55296
constexpr int SM_VTH  = SM_KL  + TILE_T*QKP*4;     // 73728
constexpr int SM_VTL  = SM_VTH + Dn*VTP*4;         // 91136
constexpr int SM_OSM  = SM_VTL + Dn*VTP*4;         // 108544
constexpr int SM_PSUM = SM_OSM + 2*TILE_T*OPITCH*4;// 182272
constexpr int SM_W    = SM_PSUM + 2*TILE_T*4;      // 183296 (16B aligned)
constexpr int SMEM_BYTES = SM_W + 32*8;            // 183552

extern __shared__ char smem[];

// ---------- packed f32x2 helpers ----------
__device__ __forceinline__ ull pk2(float lo, float hi) {
    ull r; asm("mov.b64 %0, {%1,%2};" : "=l"(r) : "f"(lo), "f"(hi)); return r;
}
__device__ __forceinline__ ull dup2(float v) { return pk2(v, v); }
__device__ __forceinline__ void un2(ull v, float& a, float& b) {
    asm("mov.b64 {%0,%1}, %2;" : "=f"(a), "=f"(b) : "l"(v));
}
__device__ __forceinline__ ull f2fma(ull a, ull b, ull c) {
    ull d; asm("fma.rn.f32x2 %0, %1, %2, %3;" : "=l"(d) : "l"(a), "l"(b), "l"(c)); return d;
}
__device__ __forceinline__ ull f2add(ull a, ull b) {
    ull d; asm("add.rn.f32x2 %0, %1, %2;" : "=l"(d) : "l"(a), "l"(b)); return d;
}
// packed exp2(s*log2e + C)
__device__ __forceinline__ ull exp2p(ull s2, ull L2E2, ull C2) {
    const ull MAG2  = dup2(12582912.0f);
    const ull NONE2 = dup2(-1.0f);
    const ull ONE2  = dup2(1.0f);
    const ull TC1   = dup2(0.69314718056f);
    const ull TC2   = dup2(0.240226507f);
    const ull TC3   = dup2(0.0555041087f);
    const ull TC4   = dup2(0.00961812911f);
    const ull TC5   = dup2(0.00133335581f);
    ull a2  = f2fma(s2, L2E2, C2);
    ull fr2 = f2add(a2, MAG2);
    ull nf2 = f2fma(MAG2, NONE2, fr2);
    ull ff2 = f2fma(nf2, NONE2, a2);
    ull p2  = f2fma(TC5, ff2, TC4);
    p2 = f2fma(p2, ff2, TC3);
    p2 = f2fma(p2, ff2, TC2);
    p2 = f2fma(p2, ff2, TC1);
    p2 = f2fma(p2, ff2, ONE2);
    float frl, frh, pl, ph;
    un2(fr2, frl, frh); un2(p2, pl, ph);
    float yl = __int_as_float(__float_as_int(pl) + (__float_as_int(frl) << 23));
    float yh = __int_as_float(__float_as_int(ph) + (__float_as_int(frh) << 23));
    return pk2(yl, yh);
}

// pack two f32 into bf16x2 (lo -> low half)
__device__ __forceinline__ uint32_t bf16x2_of(float lo, float hi) {
    uint32_t r;
    asm("cvt.rn.bf16x2.f32 %0, %1, %2;" : "=r"(r) : "f"(hi), "f"(lo));
    return r;
}

// mma.sync m16n8k16 row.col f32.bf16.bf16.f32  (sm_80+ baseline: legal at sm_103)
__device__ __forceinline__ void mma16816(float* c, const uint32_t a[4], uint32_t b0, uint32_t b1) {
    asm volatile("mma.sync.aligned.m16n8k16.row.col.f32.bf16.bf16.f32 "
        "{%0,%1,%2,%3}, {%4,%5,%6,%7}, {%8,%9}, {%0,%1,%2,%3};"
        : "+f"(c[0]), "+f"(c[1]), "+f"(c[2]), "+f"(c[3])
        : "r"(a[0]), "r"(a[1]), "r"(a[2]), "r"(a[3]), "r"(b0), "r"(b1));
}

// fp32 float4 -> bf16 hi/lo splits, stored as uint2 at byteoff
__device__ __forceinline__ void store_split(char* hib, char* lob, uint32_t byteoff, float4 v) {
    uint32_t h01 = bf16x2_of(v.x, v.y);
    uint32_t h23 = bf16x2_of(v.z, v.w);
    float r0 = v.x - __int_as_float(h01 << 16);
    float r1 = v.y - __int_as_float(h01 & 0xFFFF0000u);
    float r2 = v.z - __int_as_float(h23 << 16);
    float r3 = v.w - __int_as_float(h23 & 0xFFFF0000u);
    uint32_t l01 = bf16x2_of(r0, r1);
    uint32_t l23 = bf16x2_of(r2, r3);
    *reinterpret_cast<uint2*>(hib + byteoff) = make_uint2(h01, h23);
    *reinterpret_cast<uint2*>(lob + byteoff) = make_uint2(l01, l23);
}

__global__ __launch_bounds__(NTH, 1)
void msmha_mma_kernel(const float* __restrict__ qg, const float* __restrict__ kg,
                      const float* __restrict__ vg, const float* __restrict__ dtm,
                      const float* __restrict__ w1g, const float* __restrict__ b1g,
                      const float* __restrict__ w2g, const float* __restrict__ b2g,
                      float* __restrict__ outg)
{
    const int tt  = blockIdx.x;          // 0..3
    const int bh  = blockIdx.y;          // 0..63
    const int b   = bh >> 4;
    const int h   = bh & 15;
    const int t0  = tt * TILE_T;
    const int tid = threadIdx.x;
    const int wid = tid >> 5;
    const int lane = tid & 31;
    const int g = lane >> 2;             // fragment group row
    const int t = lane & 3;              // thread-in-group
    const int wm = wid >> 1;             // 0..7 : t16 tile
    const int wn = wid & 1;              // 0..1 : m/k half
    const int row0 = 16*wm + g;
    const int row1 = row0 + 8;

    // ---- prologue: weight table to smem + per-thread folds ----
    float Afold = 0.f, Bfold = 0.f, Cfold = 0.f;
    {
        const float* W1 = w1g + h * 2 * HIDn;
        const float* B1 = b1g + h * HIDn;
        const float* W2 = w2g + h * HIDn;
        if (tid < 8) {
            int jp = tid;
            ull* Wt = reinterpret_cast<ull*>(smem + SM_W);
            Wt[4*jp+0] = pk2(W1[2*jp],      W1[2*jp+1]);
            Wt[4*jp+1] = pk2(W1[16+2*jp],   W1[16+2*jp+1]);
            Wt[4*jp+2] = pk2(B1[2*jp],      B1[2*jp+1]);
            Wt[4*jp+3] = pk2(0.5f*W2[2*jp], 0.5f*W2[2*jp+1]);
        }
#pragma unroll
        for (int j = 0; j < 16; ++j) {
            float w2v = W2[j];
            Afold += w2v * W1[j];
            Bfold += w2v * W1[16+j];
            Cfold += w2v * B1[j];
        }
        Afold *= 0.5f; Bfold *= 0.5f; Cfold *= 0.5f;
    }
    const ull L2E2 = dup2(1.44269504f);
    const ull CEX2 = dup2((b2g[h] - 20.0f) * 1.44269504f);
    const ull ABSM = 0x7FFFFFFF7FFFFFFFull;

    // ---- Q tile load (prescaled 1/8) -> bf16 hi/lo, pitch 144B ----
    {
        const float* qsrc = qg + ((long)bh * Tn + t0) * Dn;
#pragma unroll
        for (int it = 0; it < 4; ++it) {
            int idx = tid + NTH * it;
            int row = idx >> 4, c4 = idx & 15;
            float4 v = *reinterpret_cast<const float4*>(qsrc + row * Dn + 4 * c4);
            v.x *= 0.125f; v.y *= 0.125f; v.z *= 0.125f; v.w *= 0.125f;
            store_split(smem + SM_QH, smem + SM_QL, row * 144 + c4 * 8, v);
        }
    }

    float rs0 = 0.f, rs1 = 0.f;

    for (int mc = 0; mc < NCHUNK; ++mc) {
        const int m0 = mc * MCH;
        __syncthreads();   // prev-chunk compute done before overwriting K/Vt

        // K chunk -> [m][d] bf16 hi/lo, pitch 144B
        {
            const float* ks = kg + ((long)bh * Mn + m0) * Dn;
#pragma unroll
            for (int it = 0; it < 4; ++it) {
                int idx = tid + NTH * it;
                int row = idx >> 4, c4 = idx & 15;
                float4 v = *reinterpret_cast<const float4*>(ks + row * Dn + 4 * c4);
                store_split(smem + SM_KH, smem + SM_KL, row * 144 + c4 * 8, v);
            }
        }
        // V chunk -> transposed Vt[d][m] bf16 hi/lo, pitch 272B
        {
            const float* vs = vg + ((long)bh * Mn + m0) * Dn;
#pragma unroll
            for (int it = 0; it < 4; ++it) {
                int idx = tid + NTH * it;
                int m = idx >> 4, c4 = idx & 15;
                float4 v = *reinterpret_cast<const float4*>(vs + m * Dn + 4 * c4);
                float xv[4] = {v.x, v.y, v.z, v.w};
#pragma unroll
                for (int e = 0; e < 4; ++e) {
                    int d = 4*c4 + e;
                    unsigned short hb = __bfloat16_as_ushort(__float2bfloat16_rn(xv[e]));
                    float hr = xv[e] - __int_as_float(((uint32_t)hb) << 16);
                    unsigned short lb = __bfloat16_as_ushort(__float2bfloat16_rn(hr));
                    *reinterpret_cast<unsigned short*>(smem + SM_VTH + d*272 + 2*m) = hb;
                    *reinterpret_cast<unsigned short*>(smem + SM_VTL + d*272 + 2*m) = lb;
                }
            }
        }
        __syncthreads();

        // ===== QK^T : S fragments (m16 x n64 per warp; n-slice = wn*64) =====
        float s[8][4];
#pragma unroll
        for (int i = 0; i < 8; ++i) { s[i][0]=s[i][1]=s[i][2]=s[i][3]=0.f; }
        const uint32_t* Qhw = reinterpret_cast<const uint32_t*>(smem + SM_QH);
        const uint32_t* Qlw = reinterpret_cast<const uint32_t*>(smem + SM_QL);
        const uint32_t* Khw = reinterpret_cast<const uint32_t*>(smem + SM_KH);
        const uint32_t* Klw = reinterpret_cast<const uint32_t*>(smem + SM_KL);
#pragma unroll
        for (int kc = 0; kc < 4; ++kc) {           // k16 chunks over d=64
            uint32_t ah[4], al[4];
            const int ar = (16*wm + g) * QKP + 8*kc + t;
            ah[0] = Qhw[ar];           ah[1] = Qhw[ar + 8*QKP];
            ah[2] = Qhw[ar + 4];       ah[3] = Qhw[ar + 4 + 8*QKP];
            al[0] = Qlw[ar];           al[1] = Qlw[ar + 8*QKP];
            al[2] = Qlw[ar + 4];       al[3] = Qlw[ar + 4 + 8*QKP];
#pragma unroll
            for (int ti = 0; ti < 8; ++ti) {       // n8 tiles over 64 keys
                const int br = (64*wn + 8*ti + g) * QKP + 8*kc + t;
                uint32_t kh0 = Khw[br], kh1 = Khw[br + 4];
                uint32_t kl0 = Klw[br], kl1 = Klw[br + 4];
                mma16816(s[ti], ah, kh0, kh1);
                mma16816(s[ti], ah, kl0, kl1);
                mma16816(s[ti], al, kh0, kh1);
            }
        }

        // ===== MLP + exp on fragments -> P A-fragments (hi/lo) =====
        ull wA[8], wB[8], wC[8], wH[8];
        {
            const ull* Wt = reinterpret_cast<const ull*>(smem + SM_W);
#pragma unroll
            for (int jp = 0; jp < 8; ++jp) {
                wA[jp] = Wt[4*jp]; wB[jp] = Wt[4*jp+1];
                wC[jp] = Wt[4*jp+2]; wH[jp] = Wt[4*jp+3];
            }
        }
        uint32_t ph[4][4], pl[4][4];
        const float* dbase = dtm + ((long)b * Tn + t0) * Mn + m0 + 64*wn;
#pragma unroll
        for (int ti = 0; ti < 8; ++ti) {
            const int colb = 8*ti + 2*t;
            float2 d01 = *reinterpret_cast<const float2*>(dbase + (long)row0 * Mn + colb);
            float2 d23 = *reinterpret_cast<const float2*>(dbase + (long)row1 * Mn + colb);
            float Dv[4] = {d01.x, d01.y, d23.x, d23.y};
            float pv[4];
#pragma unroll
            for (int e = 0; e < 4; ++e) {
                float dotv = s[ti][e];
                ull dd = dup2(dotv), DD = dup2(Dv[e]);
                ull acc = 0ull;
#pragma unroll
                for (int jp = 0; jp < 8; ++jp) {
                    ull x = f2fma(dd, wA[jp], f2fma(DD, wB[jp], wC[jp]));
                    acc = f2fma(x & ABSM, wH[jp], acc);
                }
                float alo, ahi; un2(acc, alo, ahi);
                pv[e] = (alo + ahi) + fmaf(dotv, Afold, fmaf(Dv[e], Bfold, Cfold));
            }
            ull y01 = exp2p(pk2(pv[0], pv[1]), L2E2, CEX2);
            ull y23 = exp2p(pk2(pv[2], pv[3]), L2E2, CEX2);
            float p0, p1, p2, p3;
            un2(y01, p0, p1); un2(y23, p2, p3);
            rs0 += p0 + p1;  rs1 += p2 + p3;
            uint32_t h01 = bf16x2_of(p0, p1);
            uint32_t h23 = bf16x2_of(p2, p3);
            float r0 = p0 - __int_as_float(h01 << 16);
            float r1 = p1 - __int_as_float(h01 & 0xFFFF0000u);
            float r2 = p2 - __int_as_float(h23 << 16);
            float r3 = p3 - __int_as_float(h23 & 0xFFFF0000u);
            uint32_t l01 = bf16x2_of(r0, r1);
            uint32_t l23 = bf16x2_of(r2, r3);
            const int kc = ti >> 1, half = (ti & 1) * 2;
            ph[kc][half] = h01; ph[kc][half+1] = h23;
            pl[kc][half] = l01; pl[kc][half+1] = l23;
        }

        // ===== P @ V : O partial (m16 x d64) over this warp's k-half =====
        float o[8][4];
#pragma unroll
        for (int i = 0; i < 8; ++i) { o[i][0]=o[i][1]=o[i][2]=o[i][3]=0.f; }
        const uint32_t* Vhw = reinterpret_cast<const uint32_t*>(smem + SM_VTH);
        const uint32_t* Vlw = reinterpret_cast<const uint32_t*>(smem + SM_VTL);
#pragma unroll
        for (int kc = 0; kc < 4; ++kc) {           // k16 over warp's 64 keys
#pragma unroll
            for (int ti = 0; ti < 8; ++ti) {       // n8 tiles over d=64
                const int br = (8*ti + g) * VTP + 32*wn + 8*kc + t;
                uint32_t vh0 = Vhw[br], vh1 = Vhw[br + 4];
                uint32_t vl0 = Vlw[br], vl1 = Vlw[br + 4];
                mma16816(o[ti], ph[kc], vh0, vh1);
                mma16816(o[ti], ph[kc], vl0, vl1);
                mma16816(o[ti], pl[kc], vh0, vh1);
            }
        }
        // accumulate O partial into smem (disjoint per thread; no race)
        {
            float* Ob = reinterpret_cast<float*>(smem + SM_OSM) + wn * TILE_T * OPITCH;
#pragma unroll
            for (int ti = 0; ti < 8; ++ti) {
                const int c = 8*ti + 2*t;
                float* p0a = Ob + row0 * OPITCH + c;
                float* p1a = Ob + row1 * OPITCH + c;
                if (mc == 0) {
                    *reinterpret_cast<float2*>(p0a) = make_float2(o[ti][0], o[ti][1]);
                    *reinterpret_cast<float2*>(p1a) = make_float2(o[ti][2], o[ti][3]);
                } else {
                    float2 a0v = *reinterpret_cast<float2*>(p0a);
                    float2 a1v = *reinterpret_cast<float2*>(p1a);
                    *reinterpret_cast<float2*>(p0a) = make_float2(a0v.x + o[ti][0], a0v.y + o[ti][1]);
                    *reinterpret_cast<float2*>(p1a) = make_float2(a1v.x + o[ti][2], a1v.y + o[ti][3]);
                }
            }
        }
    }

    // rowsums: reduce over t lanes, write per-half table
    rs0 += __shfl_xor_sync(0xffffffffu, rs0, 1);
    rs0 += __shfl_xor_sync(0xffffffffu, rs0, 2);
    rs1 += __shfl_xor_sync(0xffffffffu, rs1, 1);
    rs1 += __shfl_xor_sync(0xffffffffu, rs1, 2);
    if (t == 0) {
        float* Ps = reinterpret_cast<float*>(smem + SM_PSUM);
        Ps[wn * TILE_T + row0] = rs0;
        Ps[wn * TILE_T + row1] = rs1;
    }
    __syncthreads();

    // epilogue: reduce halves, normalize, store
    {
        const float* Ps = reinterpret_cast<const float*>(smem + SM_PSUM);
        const float* O0 = reinterpret_cast<const float*>(smem + SM_OSM);
        const float* O1 = O0 + TILE_T * OPITCH;
#pragma unroll
        for (int it = 0; it < 4; ++it) {
            int idx = tid + NTH * it;
            int row = idx >> 4, c4 = idx & 15;
            float4 a  = *reinterpret_cast<const float4*>(O0 + row * OPITCH + 4*c4);
            float4 bq = *reinterpret_cast<const float4*>(O1 + row * OPITCH + 4*c4);
            float inv = 1.0f / (Ps[row] + Ps[TILE_T + row]);
            float4 rr = make_float4((a.x+bq.x)*inv, (a.y+bq.y)*inv,
                                    (a.z+bq.z)*inv, (a.w+bq.w)*inv);
            *reinterpret_cast<float4*>(outg + ((long)b*Tn + t0 + row)*(Hn*Dn) + h*Dn + 4*c4) = rr;
        }
    }
}

extern "C" void kernel_launch(void* const* d_in, const int* in_sizes, int n_in,
                              void* d_out, int out_size)
{
    const float* q   = (const float*)d_in[0];
    const float* k   = (const float*)d_in[1];
    const float* v   = (const float*)d_in[2];
    const float* dtm = (const float*)d_in[3];
    const float* w1  = (const float*)d_in[4];
    const float* b1  = (const float*)d_in[5];
    const float* w2  = (const float*)d_in[6];
    const float* b2  = (const float*)d_in[7];
    float* out = (float*)d_out;

    cudaFuncSetAttribute(msmha_mma_kernel,
                         cudaFuncAttributeMaxDynamicSharedMemorySize, SMEM_BYTES);

    dim3 grid(Tn / TILE_T, Bn * Hn);   // (4, 64) = 256 CTAs
    msmha_mma_kernel<<<grid, NTH, SMEM_BYTES>>>(q, k, v, dtm, w1, b1, w2, b2, out);
}

// round 12
// speedup vs baseline: 3.0532x; 1.1036x over previous
#include <cuda_runtime.h>
#include <cuda_bf16.h>
#include <cstdint>

// Shapes (fixed)
#define Bn   4
#define Hn   16
#define Tn   512
#define Mn   512
#define Dn   64
#define HIDn 16

typedef unsigned long long ull;

constexpr int NTH    = 512;
constexpr int TILE_T = 128;
constexpr int MCH    = 128;
constexpr int NCHUNK = 4;

constexpr int QKP    = 36;   // words/row, Q & K bf16 tiles [128][64]  (144 B)
constexpr int VTP    = 68;   // words/row, Vt bf16 [64][128]           (272 B)
constexpr int OPITCH = 72;   // words/row, O partial smem [128][64] f32

// buffer-relative offsets (bytes)
constexpr int BUF_KH  = 0;
constexpr int BUF_KL  = BUF_KH + TILE_T*QKP*4;     // 18432
constexpr int BUF_VTH = BUF_KL + TILE_T*QKP*4;     // 36864
constexpr int BUF_VTL = BUF_VTH + Dn*VTP*4;        // 54272
constexpr int BUF_SZ  = BUF_VTL + Dn*VTP*4;        // 71680

// smem layout
constexpr int SM_QH   = 0;
constexpr int SM_QL   = SM_QH + TILE_T*QKP*4;      // 18432
constexpr int SM_BUF0 = SM_QL + TILE_T*QKP*4;      // 36864
constexpr int SM_BUF1 = SM_BUF0 + BUF_SZ;          // 108544
constexpr int SM_OSM  = SM_BUF0;                   // overlay (end only): 2*128*72*4 = 73728 <= 2*BUF_SZ
constexpr int SM_PSUM = SM_BUF1 + BUF_SZ;          // 180224
constexpr int SM_W    = SM_PSUM + 2*TILE_T*4;      // 181248
constexpr int SMEM_BYTES = SM_W + 32*8;            // 181504

extern __shared__ char smem[];

// ---------- packed f32x2 helpers ----------
__device__ __forceinline__ ull pk2(float lo, float hi) {
    ull r; asm("mov.b64 %0, {%1,%2};" : "=l"(r) : "f"(lo), "f"(hi)); return r;
}
__device__ __forceinline__ ull dup2(float v) { return pk2(v, v); }
__device__ __forceinline__ void un2(ull v, float& a, float& b) {
    asm("mov.b64 {%0,%1}, %2;" : "=f"(a), "=f"(b) : "l"(v));
}
__device__ __forceinline__ ull f2fma(ull a, ull b, ull c) {
    ull d; asm("fma.rn.f32x2 %0, %1, %2, %3;" : "=l"(d) : "l"(a), "l"(b), "l"(c)); return d;
}
__device__ __forceinline__ ull f2add(ull a, ull b) {
    ull d; asm("add.rn.f32x2 %0, %1, %2;" : "=l"(d) : "l"(a), "l"(b)); return d;
}
// packed exp2(s*log2e + C)
__device__ __forceinline__ ull exp2p(ull s2, ull L2E2, ull C2) {
    const ull MAG2  = dup2(12582912.0f);
    const ull NONE2 = dup2(-1.0f);
    const ull ONE2  = dup2(1.0f);
    const ull TC1   = dup2(0.69314718056f);
    const ull TC2   = dup2(0.240226507f);
    const ull TC3   = dup2(0.0555041087f);
    const ull TC4   = dup2(0.00961812911f);
    const ull TC5   = dup2(0.00133335581f);
    ull a2  = f2fma(s2, L2E2, C2);
    ull fr2 = f2add(a2, MAG2);
    ull nf2 = f2fma(MAG2, NONE2, fr2);
    ull ff2 = f2fma(nf2, NONE2, a2);
    ull p2  = f2fma(TC5, ff2, TC4);
    p2 = f2fma(p2, ff2, TC3);
    p2 = f2fma(p2, ff2, TC2);
    p2 = f2fma(p2, ff2, TC1);
    p2 = f2fma(p2, ff2, ONE2);
    float frl, frh, pl, ph;
    un2(fr2, frl, frh); un2(p2, pl, ph);
    float yl = __int_as_float(__float_as_int(pl) + (__float_as_int(frl) << 23));
    float yh = __int_as_float(__float_as_int(ph) + (__float_as_int(frh) << 23));
    return pk2(yl, yh);
}

// pack two f32 into bf16x2 (lo -> low half)
__device__ __forceinline__ uint32_t bf16x2_of(float lo, float hi) {
    uint32_t r;
    asm("cvt.rn.bf16x2.f32 %0, %1, %2;" : "=r"(r) : "f"(hi), "f"(lo));
    return r;
}

// mma.sync m16n8k16 row.col f32.bf16.bf16.f32
__device__ __forceinline__ void mma16816(float* c, const uint32_t a[4], uint32_t b0, uint32_t b1) {
    asm volatile("mma.sync.aligned.m16n8k16.row.col.f32.bf16.bf16.f32 "
        "{%0,%1,%2,%3}, {%4,%5,%6,%7}, {%8,%9}, {%0,%1,%2,%3};"
        : "+f"(c[0]), "+f"(c[1]), "+f"(c[2]), "+f"(c[3])
        : "r"(a[0]), "r"(a[1]), "r"(a[2]), "r"(a[3]), "r"(b0), "r"(b1));
}

// fp32 float4 -> bf16 hi/lo splits stored as uint2
__device__ __forceinline__ void store_split(char* hib, char* lob, uint32_t byteoff, float4 v) {
    uint32_t h01 = bf16x2_of(v.x, v.y);
    uint32_t h23 = bf16x2_of(v.z, v.w);
    float r0 = v.x - __int_as_float(h01 << 16);
    float r1 = v.y - __int_as_float(h01 & 0xFFFF0000u);
    float r2 = v.z - __int_as_float(h23 << 16);
    float r3 = v.w - __int_as_float(h23 & 0xFFFF0000u);
    uint32_t l01 = bf16x2_of(r0, r1);
    uint32_t l23 = bf16x2_of(r2, r3);
    *reinterpret_cast<uint2*>(hib + byteoff) = make_uint2(h01, h23);
    *reinterpret_cast<uint2*>(lob + byteoff) = make_uint2(l01, l23);
}

// load K chunk -> [m][d] bf16 hi/lo, pitch 144B
__device__ __forceinline__ void load_K(const float* __restrict__ ks, char* buf, int tid) {
#pragma unroll
    for (int it = 0; it < 4; ++it) {
        int idx = tid + NTH * it;
        int row = idx >> 4, c4 = idx & 15;
        float4 v = *reinterpret_cast<const float4*>(ks + row * Dn + 4 * c4);
        store_split(buf + BUF_KH, buf + BUF_KL, row * 144 + c4 * 8, v);
    }
}
// load V chunk -> Vt[d][m-pair] bf16x2 hi/lo, conflict-free stores
__device__ __forceinline__ void load_V(const float* __restrict__ vs, char* buf, int tid) {
    uint32_t* VtH = reinterpret_cast<uint32_t*>(buf + BUF_VTH);
    uint32_t* VtL = reinterpret_cast<uint32_t*>(buf + BUF_VTL);
#pragma unroll
    for (int it = 0; it < 4; ++it) {
        int idx = tid + NTH * it;      // 0..2047
        int mp = idx & 63;             // m-pair 0..63
        int d  = (idx >> 6) * 2;       // 0,2,..,62
        float2 va = *reinterpret_cast<const float2*>(vs + (2*mp)   * Dn + d);
        float2 vb = *reinterpret_cast<const float2*>(vs + (2*mp+1) * Dn + d);
        uint32_t h0 = bf16x2_of(va.x, vb.x);        // column d, (m=2mp, 2mp+1)
        uint32_t h1 = bf16x2_of(va.y, vb.y);        // column d+1
        float r0 = va.x - __int_as_float(h0 << 16);
        float r1 = vb.x - __int_as_float(h0 & 0xFFFF0000u);
        float r2 = va.y - __int_as_float(h1 << 16);
        float r3 = vb.y - __int_as_float(h1 & 0xFFFF0000u);
        uint32_t l0 = bf16x2_of(r0, r1);
        uint32_t l1 = bf16x2_of(r2, r3);
        VtH[d * VTP + mp]       = h0;
        VtH[(d+1) * VTP + mp]   = h1;
        VtL[d * VTP + mp]       = l0;
        VtL[(d+1) * VTP + mp]   = l1;
    }
}

__global__ __launch_bounds__(NTH, 1)
void msmha_mma_kernel(const float* __restrict__ qg, const float* __restrict__ kg,
                      const float* __restrict__ vg, const float* __restrict__ dtm,
                      const float* __restrict__ w1g, const float* __restrict__ b1g,
                      const float* __restrict__ w2g, const float* __restrict__ b2g,
                      float* __restrict__ outg)
{
    const int tt  = blockIdx.x;
    const int bh  = blockIdx.y;
    const int b   = bh >> 4;
    const int h   = bh & 15;
    const int t0  = tt * TILE_T;
    const int tid = threadIdx.x;
    const int wid = tid >> 5;
    const int lane = tid & 31;
    const int g = lane >> 2;
    const int t = lane & 3;
    const int wm = wid >> 1;
    const int wn = wid & 1;
    const int row0 = 16*wm + g;
    const int row1 = row0 + 8;

    // ---- prologue: weight table + folds ----
    float Afold = 0.f, Bfold = 0.f, Cfold = 0.f;
    {
        const float* W1 = w1g + h * 2 * HIDn;
        const float* B1 = b1g + h * HIDn;
        const float* W2 = w2g + h * HIDn;
        if (tid < 8) {
            int jp = tid;
            ull* Wt = reinterpret_cast<ull*>(smem + SM_W);
            Wt[4*jp+0] = pk2(W1[2*jp],      W1[2*jp+1]);
            Wt[4*jp+1] = pk2(W1[16+2*jp],   W1[16+2*jp+1]);
            Wt[4*jp+2] = pk2(B1[2*jp],      B1[2*jp+1]);
            Wt[4*jp+3] = pk2(0.5f*W2[2*jp], 0.5f*W2[2*jp+1]);
        }
#pragma unroll
        for (int j = 0; j < 16; ++j) {
            float w2v = W2[j];
            Afold += w2v * W1[j];
            Bfold += w2v * W1[16+j];
            Cfold += w2v * B1[j];
        }
        Afold *= 0.5f; Bfold *= 0.5f; Cfold *= 0.5f;
    }
    const ull L2E2 = dup2(1.44269504f);
    const ull CEX2 = dup2((b2g[h] - 20.0f) * 1.44269504f);
    const ull ABSM = 0x7FFFFFFF7FFFFFFFull;

    // ---- Q tile (prescaled 1/8) ----
    {
        const float* qsrc = qg + ((long)bh * Tn + t0) * Dn;
#pragma unroll
        for (int it = 0; it < 4; ++it) {
            int idx = tid + NTH * it;
            int row = idx >> 4, c4 = idx & 15;
            float4 v = *reinterpret_cast<const float4*>(qsrc + row * Dn + 4 * c4);
            v.x *= 0.125f; v.y *= 0.125f; v.z *= 0.125f; v.w *= 0.125f;
            store_split(smem + SM_QH, smem + SM_QL, row * 144 + c4 * 8, v);
        }
    }
    // preload chunk 0
    load_K(kg + (long)bh * Mn * Dn, smem + SM_BUF0, tid);
    load_V(vg + (long)bh * Mn * Dn, smem + SM_BUF0, tid);
    __syncthreads();

    float rs0 = 0.f, rs1 = 0.f;
    float o[8][4];
#pragma unroll
    for (int i = 0; i < 8; ++i) { o[i][0]=o[i][1]=o[i][2]=o[i][3]=0.f; }

    for (int mc = 0; mc < NCHUNK; ++mc) {
        char* buf = smem + ((mc & 1) ? SM_BUF1 : SM_BUF0);

        // ===== QK^T =====
        float s[8][4];
#pragma unroll
        for (int i = 0; i < 8; ++i) { s[i][0]=s[i][1]=s[i][2]=s[i][3]=0.f; }
        const uint32_t* Qhw = reinterpret_cast<const uint32_t*>(smem + SM_QH);
        const uint32_t* Qlw = reinterpret_cast<const uint32_t*>(smem + SM_QL);
        const uint32_t* Khw = reinterpret_cast<const uint32_t*>(buf + BUF_KH);
        const uint32_t* Klw = reinterpret_cast<const uint32_t*>(buf + BUF_KL);
#pragma unroll
        for (int kc = 0; kc < 4; ++kc) {
            uint32_t ah[4], al[4];
            const int ar = (16*wm + g) * QKP + 8*kc + t;
            ah[0] = Qhw[ar];       ah[1] = Qhw[ar + 8*QKP];
            ah[2] = Qhw[ar + 4];   ah[3] = Qhw[ar + 4 + 8*QKP];
            al[0] = Qlw[ar];       al[1] = Qlw[ar + 8*QKP];
            al[2] = Qlw[ar + 4];   al[3] = Qlw[ar + 4 + 8*QKP];
#pragma unroll
            for (int ti = 0; ti < 8; ++ti) {
                const int br = (64*wn + 8*ti + g) * QKP + 8*kc + t;
                uint32_t kh0 = Khw[br], kh1 = Khw[br + 4];
                uint32_t kl0 = Klw[br], kl1 = Klw[br + 4];
                mma16816(s[ti], ah, kh0, kh1);
                mma16816(s[ti], ah, kl0, kl1);
                mma16816(s[ti], al, kh0, kh1);
            }
        }

        // ===== MLP + exp -> P fragments =====
        ull wA[8], wB[8], wC[8], wH[8];
        {
            const ull* Wt = reinterpret_cast<const ull*>(smem + SM_W);
#pragma unroll
            for (int jp = 0; jp < 8; ++jp) {
                wA[jp] = Wt[4*jp]; wB[jp] = Wt[4*jp+1];
                wC[jp] = Wt[4*jp+2]; wH[jp] = Wt[4*jp+3];
            }
        }
        uint32_t ph[4][4], pl[4][4];
        const float* dbase = dtm + ((long)b * Tn + t0) * Mn + mc * MCH + 64*wn;
#pragma unroll
        for (int ti = 0; ti < 8; ++ti) {
            const int colb = 8*ti + 2*t;
            float2 d01 = *reinterpret_cast<const float2*>(dbase + (long)row0 * Mn + colb);
            float2 d23 = *reinterpret_cast<const float2*>(dbase + (long)row1 * Mn + colb);
            float Dv[4] = {d01.x, d01.y, d23.x, d23.y};
            float pv[4];
#pragma unroll
            for (int e = 0; e < 4; ++e) {
                float dotv = s[ti][e];
                ull dd = dup2(dotv), DD = dup2(Dv[e]);
                ull acc = 0ull;
#pragma unroll
                for (int jp = 0; jp < 8; ++jp) {
                    ull x = f2fma(dd, wA[jp], f2fma(DD, wB[jp], wC[jp]));
                    acc = f2fma(x & ABSM, wH[jp], acc);
                }
                float alo, ahi; un2(acc, alo, ahi);
                pv[e] = (alo + ahi) + fmaf(dotv, Afold, fmaf(Dv[e], Bfold, Cfold));
            }
            ull y01 = exp2p(pk2(pv[0], pv[1]), L2E2, CEX2);
            ull y23 = exp2p(pk2(pv[2], pv[3]), L2E2, CEX2);
            float p0, p1, p2, p3;
            un2(y01, p0, p1); un2(y23, p2, p3);
            rs0 += p0 + p1;  rs1 += p2 + p3;
            uint32_t h01 = bf16x2_of(p0, p1);
            uint32_t h23 = bf16x2_of(p2, p3);
            float r0 = p0 - __int_as_float(h01 << 16);
            float r1 = p1 - __int_as_float(h01 & 0xFFFF0000u);
            float r2 = p2 - __int_as_float(h23 << 16);
            float r3 = p3 - __int_as_float(h23 & 0xFFFF0000u);
            uint32_t l01 = bf16x2_of(r0, r1);
            uint32_t l23 = bf16x2_of(r2, r3);
            const int kc = ti >> 1, half = (ti & 1) * 2;
            ph[kc][half] = h01; ph[kc][half+1] = h23;
            pl[kc][half] = l01; pl[kc][half+1] = l23;
        }

        // ===== P @ V -> persistent O registers =====
        const uint32_t* Vhw = reinterpret_cast<const uint32_t*>(buf + BUF_VTH);
        const uint32_t* Vlw = reinterpret_cast<const uint32_t*>(buf + BUF_VTL);
#pragma unroll
        for (int kc = 0; kc < 4; ++kc) {
#pragma unroll
            for (int ti = 0; ti < 8; ++ti) {
                const int br = (8*ti + g) * VTP + 32*wn + 8*kc + t;
                uint32_t vh0 = Vhw[br], vh1 = Vhw[br + 4];
                uint32_t vl0 = Vlw[br], vl1 = Vlw[br + 4];
                mma16816(o[ti], ph[kc], vh0, vh1);
                mma16816(o[ti], ph[kc], vl0, vl1);
                mma16816(o[ti], pl[kc], vh0, vh1);
            }
        }

        // load next chunk into other buffer (overlaps other warps' compute)
        if (mc < NCHUNK - 1) {
            char* nbuf = smem + (((mc + 1) & 1) ? SM_BUF1 : SM_BUF0);
            const long base = (long)bh * Mn * Dn + (long)(mc + 1) * MCH * Dn;
            load_K(kg + base, nbuf, tid);
            load_V(vg + base, nbuf, tid);
        }
        __syncthreads();
    }

    // rowsums
    rs0 += __shfl_xor_sync(0xffffffffu, rs0, 1);
    rs0 += __shfl_xor_sync(0xffffffffu, rs0, 2);
    rs1 += __shfl_xor_sync(0xffffffffu, rs1, 1);
    rs1 += __shfl_xor_sync(0xffffffffu, rs1, 2);
    if (t == 0) {
        float* Ps = reinterpret_cast<float*>(smem + SM_PSUM);
        Ps[wn * TILE_T + row0] = rs0;
        Ps[wn * TILE_T + row1] = rs1;
    }

    // flush O registers once (overlay on buffers; all compute done after last sync)
    {
        float* Ob = reinterpret_cast<float*>(smem + SM_OSM) + wn * TILE_T * OPITCH;
#pragma unroll
        for (int ti = 0; ti < 8; ++ti) {
            const int c = 8*ti + 2*t;
            *reinterpret_cast<float2*>(Ob + row0 * OPITCH + c) = make_float2(o[ti][0], o[ti][1]);
            *reinterpret_cast<float2*>(Ob + row1 * OPITCH + c) = make_float2(o[ti][2], o[ti][3]);
        }
    }
    __syncthreads();

    // epilogue: reduce halves, normalize, store
    {
        const float* Ps = reinterpret_cast<const float*>(smem + SM_PSUM);
        const float* O0 = reinterpret_cast<const float*>(smem + SM_OSM);
        const float* O1 = O0 + TILE_T * OPITCH;
#pragma unroll
        for (int it = 0; it < 4; ++it) {
            int idx = tid + NTH * it;
            int row = idx >> 4, c4 = idx & 15;
            float4 a  = *reinterpret_cast<const float4*>(O0 + row * OPITCH + 4*c4);
            float4 bq = *reinterpret_cast<const float4*>(O1 + row * OPITCH + 4*c4);
            float inv = 1.0f / (Ps[row] + Ps[TILE_T + row]);
            float4 rr = make_float4((a.x+bq.x)*inv, (a.y+bq.y)*inv,
                                    (a.z+bq.z)*inv, (a.w+bq.w)*inv);
            *reinterpret_cast<float4*>(outg + ((long)b*Tn + t0 + row)*(Hn*Dn) + h*Dn + 4*c4) = rr;
        }
    }
}

extern "C" void kernel_launch(void* const* d_in, const int* in_sizes, int n_in,
                              void* d_out, int out_size)
{
    const float* q   = (const float*)d_in[0];
    const float* k   = (const float*)d_in[1];
    const float* v   = (const float*)d_in[2];
    const float* dtm = (const float*)d_in[3];
    const float* w1  = (const float*)d_in[4];
    const float* b1  = (const float*)d_in[5];
    const float* w2  = (const float*)d_in[6];
    const float* b2  = (const float*)d_in[7];
    float* out = (float*)d_out;

    cudaFuncSetAttribute(msmha_mma_kernel,
                         cudaFuncAttributeMaxDynamicSharedMemorySize, SMEM_BYTES);

    dim3 grid(Tn / TILE_T, Bn * Hn);   // (4, 64) = 256 CTAs
    msmha_mma_kernel<<<grid, NTH, SMEM_BYTES>>>(q, k, v, dtm, w1, b1, w2, b2, out);
}